// round 2
// baseline (speedup 1.0000x reference)
#include <cuda_runtime.h>

#define NNODES 100000
#define DDIM 256
#define KH 4
#define RR 16
#define CDIM 64            // KH*RR
#define XDIM (DDIM + CDIM) // 320

// -------- scratch (static __device__ globals; no allocs allowed) --------
__device__ float g_ZU[NNODES * CDIM];      // [N][64]  Z @ Ucat
__device__ float g_agg[NNODES * CDIM];     // [N][64]  unnormalized weighted sums
__device__ float g_segsum[NNODES * KH];    // [N][4]
__device__ float g_Ucat[DDIM * CDIM];      // [256][64]  Ucat[d][k*16+r] = U[k][d][r]
__device__ float g_W[CDIM * DDIM];         // [64][256]  W[k*16+r][d] = w_k*U[k][d][r]
__device__ float g_M1[DDIM * DDIM];        // A^T A
__device__ float g_M[DDIM * DDIM];         // I + eta*(A - A^T A A)
__device__ float g_G[XDIM * DDIM];         // [320][256]: rows 0..255 = (1-C)*M, 256..319 = C*(W@M)

// -------- helpers --------
__device__ __forceinline__ void red_add_v4(float* p, float a, float b, float c, float d) {
    asm volatile("red.global.add.v4.f32 [%0], {%1,%2,%3,%4};"
                 :: "l"(p), "f"(a), "f"(b), "f"(c), "f"(d) : "memory");
}

// -------- zero scratch accumulators --------
__global__ void k_zero() {
    int t = blockIdx.x * blockDim.x + threadIdx.x;
    if (t < NNODES * CDIM) g_agg[t] = 0.f;
    if (t < NNODES * KH)   g_segsum[t] = 0.f;
}

// -------- build Ucat and W (with head softmax) --------
__global__ void k_prep(const float* __restrict__ U, const float* __restrict__ hw) {
    float w0 = hw[0], w1 = hw[1], w2 = hw[2], w3 = hw[3];
    float mx = fmaxf(fmaxf(w0, w1), fmaxf(w2, w3));
    float e0 = __expf(w0 - mx), e1 = __expf(w1 - mx), e2 = __expf(w2 - mx), e3 = __expf(w3 - mx);
    float inv = 1.f / (e0 + e1 + e2 + e3);
    float wk[4] = {e0 * inv, e1 * inv, e2 * inv, e3 * inv};

    int t = blockIdx.x * blockDim.x + threadIdx.x;
    if (t < KH * DDIM * RR) {
        int k = t / (DDIM * RR);
        int d = (t / RR) % DDIM;
        int r = t % RR;
        float u = U[t];                       // U[k][d][r]
        g_Ucat[d * CDIM + k * RR + r] = u;
        g_W[(k * RR + r) * DDIM + d] = wk[k] * u;
    }
}

// -------- M1 = A^T A  (A = Dmat, row-major 256x256) --------
__global__ void k_m1(const float* __restrict__ A) {
    __shared__ float s1[16][16], s2[16][16];
    int tx = threadIdx.x, ty = threadIdx.y;
    float acc = 0.f;
    for (int t = 0; t < 16; t++) {
        s1[ty][tx] = A[(t * 16 + ty) * DDIM + blockIdx.y * 16 + tx];
        s2[ty][tx] = A[(t * 16 + ty) * DDIM + blockIdx.x * 16 + tx];
        __syncthreads();
#pragma unroll
        for (int kk = 0; kk < 16; kk++) acc += s1[kk][ty] * s2[kk][tx];
        __syncthreads();
    }
    g_M1[(blockIdx.y * 16 + ty) * DDIM + blockIdx.x * 16 + tx] = acc;
}

// -------- M = I + 0.5*(A - M1@A); Gtop = 0.5*M --------
__global__ void k_m2(const float* __restrict__ A) {
    __shared__ float As[16][16], Bs[16][16];
    int tx = threadIdx.x, ty = threadIdx.y;
    int i = blockIdx.y * 16 + ty, j = blockIdx.x * 16 + tx;
    float acc = 0.f;
    for (int t = 0; t < 16; t++) {
        As[ty][tx] = g_M1[i * DDIM + t * 16 + tx];
        Bs[ty][tx] = A[(t * 16 + ty) * DDIM + j];
        __syncthreads();
#pragma unroll
        for (int kk = 0; kk < 16; kk++) acc += As[ty][kk] * Bs[kk][tx];
        __syncthreads();
    }
    float m = ((i == j) ? 1.f : 0.f) + 0.5f * (A[i * DDIM + j] - acc);  // ETA=0.5
    g_M[i * DDIM + j] = m;
    g_G[i * DDIM + j] = 0.5f * m;                                       // (1-C)=0.5
}

// -------- Gbot = 0.5 * (W @ M)  (64x256) --------
__global__ void k_wm() {
    __shared__ float As[16][16], Bs[16][16];
    int tx = threadIdx.x, ty = threadIdx.y;
    int i = blockIdx.y * 16 + ty;  // 0..63
    int j = blockIdx.x * 16 + tx;  // 0..255
    float acc = 0.f;
    for (int t = 0; t < 16; t++) {
        As[ty][tx] = g_W[i * DDIM + t * 16 + tx];
        Bs[ty][tx] = g_M[(t * 16 + ty) * DDIM + j];
        __syncthreads();
#pragma unroll
        for (int kk = 0; kk < 16; kk++) acc += As[ty][kk] * Bs[kk][tx];
        __syncthreads();
    }
    g_G[(DDIM + i) * DDIM + j] = 0.5f * acc;                            // C=0.5
}

// -------- ZU = Z @ Ucat  [100000,256]x[256,64] --------
__global__ void k_zu(const float* __restrict__ Z) {
    __shared__ float As[16][128];   // [k][row]
    __shared__ float Bs[16][64];    // [k][col]
    int tid = threadIdx.x;
    int trow = tid >> 4, tcol = tid & 15;
    int rowBase = blockIdx.x * 128;
    float acc[8][4];
#pragma unroll
    for (int i = 0; i < 8; i++)
#pragma unroll
        for (int j = 0; j < 4; j++) acc[i][j] = 0.f;

    for (int kt = 0; kt < 16; kt++) {
        int k0 = kt * 16;
#pragma unroll
        for (int l = 0; l < 2; l++) {
            int f = tid + l * 256;
            int r = f >> 2, c4 = f & 3;
            int gr = rowBase + r; if (gr >= NNODES) gr = NNODES - 1;
            float4 v = *(const float4*)&Z[gr * DDIM + k0 + c4 * 4];
            As[c4 * 4 + 0][r] = v.x; As[c4 * 4 + 1][r] = v.y;
            As[c4 * 4 + 2][r] = v.z; As[c4 * 4 + 3][r] = v.w;
        }
        {
            int r = tid >> 4, c4 = tid & 15;
            *(float4*)&Bs[r][c4 * 4] = *(const float4*)&g_Ucat[(k0 + r) * CDIM + c4 * 4];
        }
        __syncthreads();
#pragma unroll
        for (int k = 0; k < 16; k++) {
            float4 a0 = *(float4*)&As[k][trow * 8];
            float4 a1 = *(float4*)&As[k][trow * 8 + 4];
            float4 b0 = *(float4*)&Bs[k][tcol * 4];
            float a[8] = {a0.x, a0.y, a0.z, a0.w, a1.x, a1.y, a1.z, a1.w};
            float b[4] = {b0.x, b0.y, b0.z, b0.w};
#pragma unroll
            for (int i = 0; i < 8; i++)
#pragma unroll
                for (int j = 0; j < 4; j++) acc[i][j] += a[i] * b[j];
        }
        __syncthreads();
    }
#pragma unroll
    for (int i = 0; i < 8; i++) {
        int gr = rowBase + trow * 8 + i;
        if (gr < NNODES) {
            float4 v = make_float4(acc[i][0], acc[i][1], acc[i][2], acc[i][3]);
            *(float4*)&g_ZU[gr * CDIM + tcol * 4] = v;
        }
    }
}

// -------- single fused edge pass: logits, exp (no max shift), segsum + weighted agg --------
__global__ void k_edge(const int* __restrict__ ei, int E) {
    int t = blockIdx.x * blockDim.x + threadIdx.x;
    if (t >= E * KH) return;
    int e = t >> 2, k = t & 3;
    int src = ei[e], dst = ei[E + e];
    const float4* zs4 = (const float4*)&g_ZU[src * CDIM + k * RR];
    const float4* zd4 = (const float4*)&g_ZU[dst * CDIM + k * RR];
    float4 s0 = zs4[0], s1 = zs4[1], s2 = zs4[2], s3 = zs4[3];
    float4 d0 = zd4[0], d1 = zd4[1], d2 = zd4[2], d3 = zd4[3];
    float dot = s0.x * d0.x + s0.y * d0.y + s0.z * d0.z + s0.w * d0.w
              + s1.x * d1.x + s1.y * d1.y + s1.z * d1.z + s1.w * d1.w
              + s2.x * d2.x + s2.y * d2.y + s2.z * d2.z + s2.w * d2.w
              + s3.x * d3.x + s3.y * d3.y + s3.z * d3.z + s3.w * d3.w;
    float el = __expf(dot * 0.25f);  // scale = 1/sqrt(R) = 0.25
    atomicAdd(&g_segsum[dst * KH + k], el);
    float* ap = &g_agg[dst * CDIM + k * RR];
    red_add_v4(ap + 0,  el * s0.x, el * s0.y, el * s0.z, el * s0.w);
    red_add_v4(ap + 4,  el * s1.x, el * s1.y, el * s1.z, el * s1.w);
    red_add_v4(ap + 8,  el * s2.x, el * s2.y, el * s2.z, el * s2.w);
    red_add_v4(ap + 12, el * s3.x, el * s3.y, el * s3.z, el * s3.w);
}

// -------- normalize agg by segment sums --------
__global__ void k_norm() {
    int t = blockIdx.x * blockDim.x + threadIdx.x;
    if (t < NNODES * CDIM) {
        int n = t >> 6, c = t & 63;
        g_agg[t] = g_agg[t] / (g_segsum[n * KH + (c >> 4)] + 1e-16f);
    }
}

// -------- fused final GEMM: out = relu([Z|Agg] @ G - 0.05) --------
__global__ void k_final(const float* __restrict__ Z, float* __restrict__ out) {
    __shared__ float As[16][128];   // [k][row]
    __shared__ float Bs[16][128];   // [k][col]
    int tid = threadIdx.x;
    int trow = tid >> 4, tcol = tid & 15;
    int rowBase = blockIdx.x * 128;
    int colBase = blockIdx.y * 128;
    float acc[8][8];
#pragma unroll
    for (int i = 0; i < 8; i++)
#pragma unroll
        for (int j = 0; j < 8; j++) acc[i][j] = 0.f;

    for (int kt = 0; kt < XDIM / 16; kt++) {
        int k0 = kt * 16;
        const float* Aptr; int ld, koff;
        if (k0 < DDIM) { Aptr = Z;     ld = DDIM; koff = k0; }
        else           { Aptr = g_agg; ld = CDIM; koff = k0 - DDIM; }
#pragma unroll
        for (int l = 0; l < 2; l++) {
            int f = tid + l * 256;
            int r = f >> 2, c4 = f & 3;
            int gr = rowBase + r; if (gr >= NNODES) gr = NNODES - 1;
            float4 v = *(const float4*)&Aptr[gr * ld + koff + c4 * 4];
            As[c4 * 4 + 0][r] = v.x; As[c4 * 4 + 1][r] = v.y;
            As[c4 * 4 + 2][r] = v.z; As[c4 * 4 + 3][r] = v.w;
        }
#pragma unroll
        for (int l = 0; l < 2; l++) {
            int f = tid + l * 256;
            int r = f >> 5, c4 = f & 31;
            *(float4*)&Bs[r][c4 * 4] = *(const float4*)&g_G[(k0 + r) * DDIM + colBase + c4 * 4];
        }
        __syncthreads();
#pragma unroll
        for (int k = 0; k < 16; k++) {
            float4 a0 = *(float4*)&As[k][trow * 8];
            float4 a1 = *(float4*)&As[k][trow * 8 + 4];
            float4 b0 = *(float4*)&Bs[k][tcol * 8];
            float4 b1 = *(float4*)&Bs[k][tcol * 8 + 4];
            float a[8] = {a0.x, a0.y, a0.z, a0.w, a1.x, a1.y, a1.z, a1.w};
            float b[8] = {b0.x, b0.y, b0.z, b0.w, b1.x, b1.y, b1.z, b1.w};
#pragma unroll
            for (int i = 0; i < 8; i++)
#pragma unroll
                for (int j = 0; j < 8; j++) acc[i][j] += a[i] * b[j];
        }
        __syncthreads();
    }
#pragma unroll
    for (int i = 0; i < 8; i++) {
        int gr = rowBase + trow * 8 + i;
        if (gr < NNODES) {
            float4 o0 = make_float4(fmaxf(acc[i][0] - 0.05f, 0.f), fmaxf(acc[i][1] - 0.05f, 0.f),
                                    fmaxf(acc[i][2] - 0.05f, 0.f), fmaxf(acc[i][3] - 0.05f, 0.f));
            float4 o1 = make_float4(fmaxf(acc[i][4] - 0.05f, 0.f), fmaxf(acc[i][5] - 0.05f, 0.f),
                                    fmaxf(acc[i][6] - 0.05f, 0.f), fmaxf(acc[i][7] - 0.05f, 0.f));
            *(float4*)&out[gr * DDIM + colBase + tcol * 8]     = o0;
            *(float4*)&out[gr * DDIM + colBase + tcol * 8 + 4] = o1;
        }
    }
}

extern "C" void kernel_launch(void* const* d_in, const int* in_sizes, int n_in,
                              void* d_out, int out_size) {
    const float* Z    = (const float*)d_in[0];
    const float* U    = (const float*)d_in[1];
    const float* Dmat = (const float*)d_in[2];
    const float* hw   = (const float*)d_in[3];
    const int*   ei   = (const int*)d_in[4];
    int E = in_sizes[4] / 2;
    float* out = (float*)d_out;

    dim3 b16(16, 16);
    k_zero<<<(NNODES * CDIM + 255) / 256, 256>>>();
    k_prep<<<(KH * DDIM * RR + 255) / 256, 256>>>(U, hw);
    k_m1<<<dim3(16, 16), b16>>>(Dmat);
    k_m2<<<dim3(16, 16), b16>>>(Dmat);
    k_wm<<<dim3(16, 4), b16>>>();
    k_zu<<<(NNODES + 127) / 128, 256>>>(Z);
    k_edge<<<(E * KH + 255) / 256, 256>>>(ei, E);
    k_norm<<<(NNODES * CDIM + 255) / 256, 256>>>();
    k_final<<<dim3((NNODES + 127) / 128, DDIM / 128), 256>>>(Z, out);
}

// round 3
// speedup vs baseline: 1.1543x; 1.1543x over previous
#include <cuda_runtime.h>

#define NNODES 100000
#define DDIM 256
#define KH 4
#define RR 16
#define CDIM 64            // KH*RR
#define XDIM (DDIM + CDIM) // 320
#define EMAX 1700000
#define NBLK_SCAN 98       // ceil(NNODES/1024)

// -------- scratch (static __device__ globals; no allocs allowed) --------
__device__ float g_ZU[NNODES * CDIM];      // [N][64]  Z @ Ucat
__device__ float g_agg[NNODES * CDIM];     // [N][64]  normalized weighted sums
__device__ float g_Ucat[DDIM * CDIM];      // [256][64]
__device__ float g_W[CDIM * DDIM];         // [64][256]
__device__ float g_M1[DDIM * DDIM];        // A^T A
__device__ float g_M[DDIM * DDIM];         // I + eta*(A - A^T A A)
__device__ float g_G[XDIM * DDIM];         // [320][256]
// CSR machinery
__device__ int g_cnt[NNODES];
__device__ int g_off[NNODES + 1];
__device__ int g_cursor[NNODES];
__device__ int g_bsum[NBLK_SCAN];
__device__ int g_bpre[NBLK_SCAN];
__device__ int g_srcl[EMAX];

// -------- build Ucat and W (with head softmax) --------
__global__ void k_prep(const float* __restrict__ U, const float* __restrict__ hw) {
    float w0 = hw[0], w1 = hw[1], w2 = hw[2], w3 = hw[3];
    float mx = fmaxf(fmaxf(w0, w1), fmaxf(w2, w3));
    float e0 = __expf(w0 - mx), e1 = __expf(w1 - mx), e2 = __expf(w2 - mx), e3 = __expf(w3 - mx);
    float inv = 1.f / (e0 + e1 + e2 + e3);
    float wk[4] = {e0 * inv, e1 * inv, e2 * inv, e3 * inv};

    int t = blockIdx.x * blockDim.x + threadIdx.x;
    if (t < KH * DDIM * RR) {
        int k = t / (DDIM * RR);
        int d = (t / RR) % DDIM;
        int r = t % RR;
        float u = U[t];
        g_Ucat[d * CDIM + k * RR + r] = u;
        g_W[(k * RR + r) * DDIM + d] = wk[k] * u;
    }
}

// -------- M1 = A^T A --------
__global__ void k_m1(const float* __restrict__ A) {
    __shared__ float s1[16][16], s2[16][16];
    int tx = threadIdx.x, ty = threadIdx.y;
    float acc = 0.f;
    for (int t = 0; t < 16; t++) {
        s1[ty][tx] = A[(t * 16 + ty) * DDIM + blockIdx.y * 16 + tx];
        s2[ty][tx] = A[(t * 16 + ty) * DDIM + blockIdx.x * 16 + tx];
        __syncthreads();
#pragma unroll
        for (int kk = 0; kk < 16; kk++) acc += s1[kk][ty] * s2[kk][tx];
        __syncthreads();
    }
    g_M1[(blockIdx.y * 16 + ty) * DDIM + blockIdx.x * 16 + tx] = acc;
}

// -------- M = I + 0.5*(A - M1@A); Gtop = 0.5*M --------
__global__ void k_m2(const float* __restrict__ A) {
    __shared__ float As[16][16], Bs[16][16];
    int tx = threadIdx.x, ty = threadIdx.y;
    int i = blockIdx.y * 16 + ty, j = blockIdx.x * 16 + tx;
    float acc = 0.f;
    for (int t = 0; t < 16; t++) {
        As[ty][tx] = g_M1[i * DDIM + t * 16 + tx];
        Bs[ty][tx] = A[(t * 16 + ty) * DDIM + j];
        __syncthreads();
#pragma unroll
        for (int kk = 0; kk < 16; kk++) acc += As[ty][kk] * Bs[kk][tx];
        __syncthreads();
    }
    float m = ((i == j) ? 1.f : 0.f) + 0.5f * (A[i * DDIM + j] - acc);  // ETA=0.5
    g_M[i * DDIM + j] = m;
    g_G[i * DDIM + j] = 0.5f * m;                                       // (1-C)=0.5
}

// -------- Gbot = 0.5 * (W @ M) --------
__global__ void k_wm() {
    __shared__ float As[16][16], Bs[16][16];
    int tx = threadIdx.x, ty = threadIdx.y;
    int i = blockIdx.y * 16 + ty;
    int j = blockIdx.x * 16 + tx;
    float acc = 0.f;
    for (int t = 0; t < 16; t++) {
        As[ty][tx] = g_W[i * DDIM + t * 16 + tx];
        Bs[ty][tx] = g_M[(t * 16 + ty) * DDIM + j];
        __syncthreads();
#pragma unroll
        for (int kk = 0; kk < 16; kk++) acc += As[ty][kk] * Bs[kk][tx];
        __syncthreads();
    }
    g_G[(DDIM + i) * DDIM + j] = 0.5f * acc;                            // C=0.5
}

// -------- ZU = Z @ Ucat --------
__global__ void k_zu(const float* __restrict__ Z) {
    __shared__ float As[16][128];
    __shared__ float Bs[16][64];
    int tid = threadIdx.x;
    int trow = tid >> 4, tcol = tid & 15;
    int rowBase = blockIdx.x * 128;
    float acc[8][4];
#pragma unroll
    for (int i = 0; i < 8; i++)
#pragma unroll
        for (int j = 0; j < 4; j++) acc[i][j] = 0.f;

    for (int kt = 0; kt < 16; kt++) {
        int k0 = kt * 16;
#pragma unroll
        for (int l = 0; l < 2; l++) {
            int f = tid + l * 256;
            int r = f >> 2, c4 = f & 3;
            int gr = rowBase + r; if (gr >= NNODES) gr = NNODES - 1;
            float4 v = *(const float4*)&Z[gr * DDIM + k0 + c4 * 4];
            As[c4 * 4 + 0][r] = v.x; As[c4 * 4 + 1][r] = v.y;
            As[c4 * 4 + 2][r] = v.z; As[c4 * 4 + 3][r] = v.w;
        }
        {
            int r = tid >> 4, c4 = tid & 15;
            *(float4*)&Bs[r][c4 * 4] = *(const float4*)&g_Ucat[(k0 + r) * CDIM + c4 * 4];
        }
        __syncthreads();
#pragma unroll
        for (int k = 0; k < 16; k++) {
            float4 a0 = *(float4*)&As[k][trow * 8];
            float4 a1 = *(float4*)&As[k][trow * 8 + 4];
            float4 b0 = *(float4*)&Bs[k][tcol * 4];
            float a[8] = {a0.x, a0.y, a0.z, a0.w, a1.x, a1.y, a1.z, a1.w};
            float b[4] = {b0.x, b0.y, b0.z, b0.w};
#pragma unroll
            for (int i = 0; i < 8; i++)
#pragma unroll
                for (int j = 0; j < 4; j++) acc[i][j] += a[i] * b[j];
        }
        __syncthreads();
    }
#pragma unroll
    for (int i = 0; i < 8; i++) {
        int gr = rowBase + trow * 8 + i;
        if (gr < NNODES) {
            float4 v = make_float4(acc[i][0], acc[i][1], acc[i][2], acc[i][3]);
            *(float4*)&g_ZU[gr * CDIM + tcol * 4] = v;
        }
    }
}

// ======== CSR build ========
__global__ void k_cz() {
    int t = blockIdx.x * blockDim.x + threadIdx.x;
    if (t < NNODES) g_cnt[t] = 0;
}

__global__ void k_hist(const int* __restrict__ ei, int E) {
    int t = blockIdx.x * blockDim.x + threadIdx.x;
    if (t < E) atomicAdd(&g_cnt[ei[E + t]], 1);
}

// block scans 1024 counts (256 thr x 4), writes exclusive prefixes + block sum
__global__ void k_scan1() {
    __shared__ int s_warp[8];
    int b = blockIdx.x, t = threadIdx.x;
    int base = b * 1024 + t * 4;
    int v[4];
#pragma unroll
    for (int i = 0; i < 4; i++) { int idx = base + i; v[i] = (idx < NNODES) ? g_cnt[idx] : 0; }
    int sum = v[0] + v[1] + v[2] + v[3];
    int lane = t & 31, wid = t >> 5;
    int x = sum;
#pragma unroll
    for (int o = 1; o < 32; o <<= 1) { int y = __shfl_up_sync(0xffffffff, x, o); if (lane >= o) x += y; }
    if (lane == 31) s_warp[wid] = x;
    __syncthreads();
    if (wid == 0) {
        int w = (lane < 8) ? s_warp[lane] : 0;
#pragma unroll
        for (int o = 1; o < 8; o <<= 1) { int y = __shfl_up_sync(0xffffffff, w, o); if (lane >= o) w += y; }
        if (lane < 8) s_warp[lane] = w;
    }
    __syncthreads();
    int warppre = (wid > 0) ? s_warp[wid - 1] : 0;
    int run = warppre + x - sum;  // exclusive prefix for this thread
#pragma unroll
    for (int i = 0; i < 4; i++) { int idx = base + i; if (idx < NNODES) g_off[idx] = run; run += v[i]; }
    if (t == 255) g_bsum[b] = warppre + x;
}

__global__ void k_scan2() {  // 1 block, 128 threads, scans NBLK_SCAN block sums
    __shared__ int sw[4];
    int t = threadIdx.x;
    int v = (t < NBLK_SCAN) ? g_bsum[t] : 0;
    int lane = t & 31, wid = t >> 5;
    int x = v;
#pragma unroll
    for (int o = 1; o < 32; o <<= 1) { int y = __shfl_up_sync(0xffffffff, x, o); if (lane >= o) x += y; }
    if (lane == 31) sw[wid] = x;
    __syncthreads();
    if (t == 0) { int a = 0; for (int i = 0; i < 4; i++) { int tmp = sw[i]; sw[i] = a; a += tmp; } }
    __syncthreads();
    if (t < NBLK_SCAN) g_bpre[t] = sw[wid] + x - v;
}

__global__ void k_scan3(int E) {
    int t = blockIdx.x * blockDim.x + threadIdx.x;
    if (t < NNODES) {
        int o = g_off[t] + g_bpre[t >> 10];
        g_off[t] = o;
        g_cursor[t] = o;
    }
    if (t == 0) g_off[NNODES] = E;
}

__global__ void k_scatter(const int* __restrict__ ei, int E) {
    int t = blockIdx.x * blockDim.x + threadIdx.x;
    if (t < E) {
        int dst = ei[E + t];
        int pos = atomicAdd(&g_cursor[dst], 1);
        g_srcl[pos] = ei[t];
    }
}

// ======== warp-per-node gather/softmax/aggregate (no float atomics) ========
__global__ void k_agg() {
    int warp = (blockIdx.x * blockDim.x + threadIdx.x) >> 5;
    if (warp >= NNODES) return;
    int l = threadIdx.x & 31;
    float2 zd = *(const float2*)&g_ZU[warp * CDIM + l * 2];
    float ax = 0.f, ay = 0.f, ss = 0.f;
    int i = g_off[warp], end = g_off[warp + 1];
    for (; i + 1 < end; i += 2) {
        int s0 = g_srcl[i], s1 = g_srcl[i + 1];
        float2 a = *(const float2*)&g_ZU[s0 * CDIM + l * 2];
        float2 b = *(const float2*)&g_ZU[s1 * CDIM + l * 2];
        float p0 = a.x * zd.x + a.y * zd.y;
        float p1 = b.x * zd.x + b.y * zd.y;
        p0 += __shfl_xor_sync(0xffffffff, p0, 1);  p1 += __shfl_xor_sync(0xffffffff, p1, 1);
        p0 += __shfl_xor_sync(0xffffffff, p0, 2);  p1 += __shfl_xor_sync(0xffffffff, p1, 2);
        p0 += __shfl_xor_sync(0xffffffff, p0, 4);  p1 += __shfl_xor_sync(0xffffffff, p1, 4);
        float e0 = __expf(p0 * 0.25f), e1 = __expf(p1 * 0.25f);
        ss += e0 + e1;
        ax += e0 * a.x + e1 * b.x;
        ay += e0 * a.y + e1 * b.y;
    }
    if (i < end) {
        int s0 = g_srcl[i];
        float2 a = *(const float2*)&g_ZU[s0 * CDIM + l * 2];
        float p0 = a.x * zd.x + a.y * zd.y;
        p0 += __shfl_xor_sync(0xffffffff, p0, 1);
        p0 += __shfl_xor_sync(0xffffffff, p0, 2);
        p0 += __shfl_xor_sync(0xffffffff, p0, 4);
        float e0 = __expf(p0 * 0.25f);
        ss += e0; ax += e0 * a.x; ay += e0 * a.y;
    }
    float inv = 1.f / (ss + 1e-16f);
    *(float2*)&g_agg[warp * CDIM + l * 2] = make_float2(ax * inv, ay * inv);
}

// -------- fused final GEMM: out = relu([Z|Agg] @ G - 0.05) --------
__global__ void k_final(const float* __restrict__ Z, float* __restrict__ out) {
    __shared__ float As[16][128];
    __shared__ float Bs[16][128];
    int tid = threadIdx.x;
    int trow = tid >> 4, tcol = tid & 15;
    int rowBase = blockIdx.x * 128;
    int colBase = blockIdx.y * 128;
    float acc[8][8];
#pragma unroll
    for (int i = 0; i < 8; i++)
#pragma unroll
        for (int j = 0; j < 8; j++) acc[i][j] = 0.f;

    for (int kt = 0; kt < XDIM / 16; kt++) {
        int k0 = kt * 16;
        const float* Aptr; int ld, koff;
        if (k0 < DDIM) { Aptr = Z;     ld = DDIM; koff = k0; }
        else           { Aptr = g_agg; ld = CDIM; koff = k0 - DDIM; }
#pragma unroll
        for (int l = 0; l < 2; l++) {
            int f = tid + l * 256;
            int r = f >> 2, c4 = f & 3;
            int gr = rowBase + r; if (gr >= NNODES) gr = NNODES - 1;
            float4 v = *(const float4*)&Aptr[gr * ld + koff + c4 * 4];
            As[c4 * 4 + 0][r] = v.x; As[c4 * 4 + 1][r] = v.y;
            As[c4 * 4 + 2][r] = v.z; As[c4 * 4 + 3][r] = v.w;
        }
#pragma unroll
        for (int l = 0; l < 2; l++) {
            int f = tid + l * 256;
            int r = f >> 5, c4 = f & 31;
            *(float4*)&Bs[r][c4 * 4] = *(const float4*)&g_G[(k0 + r) * DDIM + colBase + c4 * 4];
        }
        __syncthreads();
#pragma unroll
        for (int k = 0; k < 16; k++) {
            float4 a0 = *(float4*)&As[k][trow * 8];
            float4 a1 = *(float4*)&As[k][trow * 8 + 4];
            float4 b0 = *(float4*)&Bs[k][tcol * 8];
            float4 b1 = *(float4*)&Bs[k][tcol * 8 + 4];
            float a[8] = {a0.x, a0.y, a0.z, a0.w, a1.x, a1.y, a1.z, a1.w};
            float b[8] = {b0.x, b0.y, b0.z, b0.w, b1.x, b1.y, b1.z, b1.w};
#pragma unroll
            for (int i = 0; i < 8; i++)
#pragma unroll
                for (int j = 0; j < 8; j++) acc[i][j] += a[i] * b[j];
        }
        __syncthreads();
    }
#pragma unroll
    for (int i = 0; i < 8; i++) {
        int gr = rowBase + trow * 8 + i;
        if (gr < NNODES) {
            float4 o0 = make_float4(fmaxf(acc[i][0] - 0.05f, 0.f), fmaxf(acc[i][1] - 0.05f, 0.f),
                                    fmaxf(acc[i][2] - 0.05f, 0.f), fmaxf(acc[i][3] - 0.05f, 0.f));
            float4 o1 = make_float4(fmaxf(acc[i][4] - 0.05f, 0.f), fmaxf(acc[i][5] - 0.05f, 0.f),
                                    fmaxf(acc[i][6] - 0.05f, 0.f), fmaxf(acc[i][7] - 0.05f, 0.f));
            *(float4*)&out[gr * DDIM + colBase + tcol * 8]     = o0;
            *(float4*)&out[gr * DDIM + colBase + tcol * 8 + 4] = o1;
        }
    }
}

extern "C" void kernel_launch(void* const* d_in, const int* in_sizes, int n_in,
                              void* d_out, int out_size) {
    const float* Z    = (const float*)d_in[0];
    const float* U    = (const float*)d_in[1];
    const float* Dmat = (const float*)d_in[2];
    const float* hw   = (const float*)d_in[3];
    const int*   ei   = (const int*)d_in[4];
    int E = in_sizes[4] / 2;
    float* out = (float*)d_out;

    dim3 b16(16, 16);
    k_prep<<<(KH * DDIM * RR + 255) / 256, 256>>>(U, hw);
    k_m1<<<dim3(16, 16), b16>>>(Dmat);
    k_m2<<<dim3(16, 16), b16>>>(Dmat);
    k_wm<<<dim3(16, 4), b16>>>();
    // CSR build (independent of ZU)
    k_cz<<<(NNODES + 255) / 256, 256>>>();
    k_hist<<<(E + 255) / 256, 256>>>(ei, E);
    k_scan1<<<NBLK_SCAN, 256>>>();
    k_scan2<<<1, 128>>>();
    k_scan3<<<(NNODES + 255) / 256, 256>>>(E);
    k_scatter<<<(E + 255) / 256, 256>>>(ei, E);
    // projections + gather-aggregate
    k_zu<<<(NNODES + 127) / 128, 256>>>(Z);
    k_agg<<<(NNODES * 32 + 255) / 256, 256>>>();
    k_final<<<dim3((NNODES + 127) / 128, DDIM / 128), 256>>>(Z, out);
}

// round 7
// speedup vs baseline: 1.3489x; 1.1687x over previous
#include <cuda_runtime.h>
#include <cstdint>

#define NNODES 100000
#define DDIM 256
#define KH 4
#define RR 16
#define CDIM 64            // KH*RR
#define XDIM (DDIM + CDIM) // 320
#define EMAX 1700000
#define NBLK_SCAN 98       // ceil(NNODES/1024)

// -------- scratch --------
__device__ float g_ZU[NNODES * CDIM];
__device__ float g_agg[NNODES * CDIM];
__device__ float g_Uh[DDIM * CDIM];        // Ucat hi (tf32 bits as float)
__device__ float g_Ul[DDIM * CDIM];        // Ucat lo
__device__ float g_W[CDIM * DDIM];
__device__ float g_M1[DDIM * DDIM];
__device__ float g_M[DDIM * DDIM];
__device__ float g_Gh[XDIM * DDIM];        // G hi
__device__ float g_Gl[XDIM * DDIM];        // G lo
// CSR
__device__ int g_cnt[NNODES];
__device__ int g_off[NNODES + 1];
__device__ int g_cursor[NNODES];
__device__ int g_bsum[NBLK_SCAN];
__device__ int g_bpre[NBLK_SCAN];
__device__ int g_srcl[EMAX];

// -------- tf32 helpers --------
__device__ __forceinline__ uint32_t f2tf(float x) {
    uint32_t u; asm("cvt.rna.tf32.f32 %0, %1;" : "=r"(u) : "f"(x)); return u;
}
__device__ __forceinline__ void tf_split(float x, float& hi, float& lo) {
    uint32_t uh = f2tf(x);
    hi = __uint_as_float(uh);
    lo = __uint_as_float(f2tf(x - hi));
}
__device__ __forceinline__ void mma8(float* d, const uint32_t* a, const uint32_t* b) {
    asm volatile(
        "mma.sync.aligned.m16n8k8.row.col.f32.tf32.tf32.f32 "
        "{%0,%1,%2,%3},{%4,%5,%6,%7},{%8,%9},{%0,%1,%2,%3};"
        : "+f"(d[0]), "+f"(d[1]), "+f"(d[2]), "+f"(d[3])
        : "r"(a[0]), "r"(a[1]), "r"(a[2]), "r"(a[3]), "r"(b[0]), "r"(b[1]));
}

// -------- build Ucat(hi/lo) and W (with head softmax) --------
__global__ void k_prep(const float* __restrict__ U, const float* __restrict__ hw) {
    float w0 = hw[0], w1 = hw[1], w2 = hw[2], w3 = hw[3];
    float mx = fmaxf(fmaxf(w0, w1), fmaxf(w2, w3));
    float e0 = __expf(w0 - mx), e1 = __expf(w1 - mx), e2 = __expf(w2 - mx), e3 = __expf(w3 - mx);
    float inv = 1.f / (e0 + e1 + e2 + e3);
    float wk[4] = {e0 * inv, e1 * inv, e2 * inv, e3 * inv};

    int t = blockIdx.x * blockDim.x + threadIdx.x;
    if (t < KH * DDIM * RR) {
        int k = t / (DDIM * RR);
        int d = (t / RR) % DDIM;
        int r = t % RR;
        float u = U[t];
        float hi, lo; tf_split(u, hi, lo);
        g_Uh[d * CDIM + k * RR + r] = hi;
        g_Ul[d * CDIM + k * RR + r] = lo;
        g_W[(k * RR + r) * DDIM + d] = wk[k] * u;
    }
}

// -------- M1 = A^T A (32x32 tiles) --------
__global__ void k_m1(const float* __restrict__ A) {
    __shared__ float s1[16][33], s2[16][33];
    int tid = threadIdx.x;
    int tx = tid & 15, ty = tid >> 4;
    int i0 = blockIdx.y * 32, j0 = blockIdx.x * 32;
    float c00 = 0, c01 = 0, c10 = 0, c11 = 0;
    for (int t0 = 0; t0 < 256; t0 += 16) {
#pragma unroll
        for (int l = 0; l < 2; l++) {
            int f = tid + l * 256;
            int r = f >> 5, col = f & 31;   // r spans 0..15 across both iterations
            s1[r][col] = A[(t0 + r) * DDIM + i0 + col];
            s2[r][col] = A[(t0 + r) * DDIM + j0 + col];
        }
        __syncthreads();
#pragma unroll
        for (int kk = 0; kk < 16; kk++) {
            float a0 = s1[kk][ty * 2], a1 = s1[kk][ty * 2 + 1];
            float b0 = s2[kk][tx * 2], b1 = s2[kk][tx * 2 + 1];
            c00 += a0 * b0; c01 += a0 * b1; c10 += a1 * b0; c11 += a1 * b1;
        }
        __syncthreads();
    }
    int i = i0 + ty * 2, j = j0 + tx * 2;
    g_M1[i * DDIM + j] = c00;       g_M1[i * DDIM + j + 1] = c01;
    g_M1[(i + 1) * DDIM + j] = c10; g_M1[(i + 1) * DDIM + j + 1] = c11;
}

// -------- M = I + 0.5*(A - M1@A); Gtop = 0.5*M (split) --------
__global__ void k_m2(const float* __restrict__ A) {
    __shared__ float s1[16][33], s2[16][33];   // s1[t][i] = M1[i][t], s2[t][j] = A[t][j]
    int tid = threadIdx.x;
    int tx = tid & 15, ty = tid >> 4;
    int i0 = blockIdx.y * 32, j0 = blockIdx.x * 32;
    float c00 = 0, c01 = 0, c10 = 0, c11 = 0;
    for (int t0 = 0; t0 < 256; t0 += 16) {
#pragma unroll
        for (int l = 0; l < 2; l++) {
            int f = tid + l * 256;
            int tt = f & 15, ii = f >> 4;   // ii 0..31
            s1[tt][ii] = g_M1[(i0 + ii) * DDIM + t0 + tt];
            int r = f >> 5, col = f & 31;   // r spans 0..15
            s2[r][col] = A[(t0 + r) * DDIM + j0 + col];
        }
        __syncthreads();
#pragma unroll
        for (int kk = 0; kk < 16; kk++) {
            float a0 = s1[kk][ty * 2], a1 = s1[kk][ty * 2 + 1];
            float b0 = s2[kk][tx * 2], b1 = s2[kk][tx * 2 + 1];
            c00 += a0 * b0; c01 += a0 * b1; c10 += a1 * b0; c11 += a1 * b1;
        }
        __syncthreads();
    }
    int i = i0 + ty * 2, j = j0 + tx * 2;
#pragma unroll
    for (int a = 0; a < 2; a++)
#pragma unroll
        for (int b = 0; b < 2; b++) {
            float acc = (a == 0) ? (b == 0 ? c00 : c01) : (b == 0 ? c10 : c11);
            int ii = i + a, jj = j + b;
            float m = ((ii == jj) ? 1.f : 0.f) + 0.5f * (A[ii * DDIM + jj] - acc);  // ETA=0.5
            g_M[ii * DDIM + jj] = m;
            float hi, lo; tf_split(0.5f * m, hi, lo);                               // (1-C)=0.5
            g_Gh[ii * DDIM + jj] = hi;
            g_Gl[ii * DDIM + jj] = lo;
        }
}

// -------- Gbot = 0.5 * (W @ M) (split) --------
__global__ void k_wm() {
    __shared__ float s1[16][33], s2[16][33];   // s1[t][i] = W[i][t], s2[t][j] = M[t][j]
    int tid = threadIdx.x;
    int tx = tid & 15, ty = tid >> 4;
    int i0 = blockIdx.y * 32, j0 = blockIdx.x * 32;
    float c00 = 0, c01 = 0, c10 = 0, c11 = 0;
    for (int t0 = 0; t0 < 256; t0 += 16) {
#pragma unroll
        for (int l = 0; l < 2; l++) {
            int f = tid + l * 256;
            int tt = f & 15, ii = f >> 4;
            s1[tt][ii] = g_W[(i0 + ii) * DDIM + t0 + tt];
            int r = f >> 5, col = f & 31;   // r spans 0..15
            s2[r][col] = g_M[(t0 + r) * DDIM + j0 + col];
        }
        __syncthreads();
#pragma unroll
        for (int kk = 0; kk < 16; kk++) {
            float a0 = s1[kk][ty * 2], a1 = s1[kk][ty * 2 + 1];
            float b0 = s2[kk][tx * 2], b1 = s2[kk][tx * 2 + 1];
            c00 += a0 * b0; c01 += a0 * b1; c10 += a1 * b0; c11 += a1 * b1;
        }
        __syncthreads();
    }
    int i = i0 + ty * 2, j = j0 + tx * 2;
#pragma unroll
    for (int a = 0; a < 2; a++)
#pragma unroll
        for (int b = 0; b < 2; b++) {
            float acc = (a == 0) ? (b == 0 ? c00 : c01) : (b == 0 ? c10 : c11);
            float hi, lo; tf_split(0.5f * acc, hi, lo);                             // C=0.5
            g_Gh[(DDIM + i + a) * DDIM + j + b] = hi;
            g_Gl[(DDIM + i + a) * DDIM + j + b] = lo;
        }
}

// ======== CSR build ========
__global__ void k_cz() {
    int t = blockIdx.x * blockDim.x + threadIdx.x;
    if (t < NNODES) g_cnt[t] = 0;
}
__global__ void k_hist(const int* __restrict__ ei, int E) {
    int t = blockIdx.x * blockDim.x + threadIdx.x;
    if (t < E) atomicAdd(&g_cnt[ei[E + t]], 1);
}
__global__ void k_scan1() {
    __shared__ int s_warp[8];
    int b = blockIdx.x, t = threadIdx.x;
    int base = b * 1024 + t * 4;
    int v[4];
#pragma unroll
    for (int i = 0; i < 4; i++) { int idx = base + i; v[i] = (idx < NNODES) ? g_cnt[idx] : 0; }
    int sum = v[0] + v[1] + v[2] + v[3];
    int lane = t & 31, wid = t >> 5;
    int x = sum;
#pragma unroll
    for (int o = 1; o < 32; o <<= 1) { int y = __shfl_up_sync(0xffffffff, x, o); if (lane >= o) x += y; }
    if (lane == 31) s_warp[wid] = x;
    __syncthreads();
    if (wid == 0) {
        int w = (lane < 8) ? s_warp[lane] : 0;
#pragma unroll
        for (int o = 1; o < 8; o <<= 1) { int y = __shfl_up_sync(0xffffffff, w, o); if (lane >= o) w += y; }
        if (lane < 8) s_warp[lane] = w;
    }
    __syncthreads();
    int warppre = (wid > 0) ? s_warp[wid - 1] : 0;
    int run = warppre + x - sum;
#pragma unroll
    for (int i = 0; i < 4; i++) { int idx = base + i; if (idx < NNODES) g_off[idx] = run; run += v[i]; }
    if (t == 255) g_bsum[b] = warppre + x;
}
__global__ void k_scan2() {
    __shared__ int sw[4];
    int t = threadIdx.x;
    int v = (t < NBLK_SCAN) ? g_bsum[t] : 0;
    int lane = t & 31, wid = t >> 5;
    int x = v;
#pragma unroll
    for (int o = 1; o < 32; o <<= 1) { int y = __shfl_up_sync(0xffffffff, x, o); if (lane >= o) x += y; }
    if (lane == 31) sw[wid] = x;
    __syncthreads();
    if (t == 0) { int a = 0; for (int i = 0; i < 4; i++) { int tmp = sw[i]; sw[i] = a; a += tmp; } }
    __syncthreads();
    if (t < NBLK_SCAN) g_bpre[t] = sw[wid] + x - v;
}
__global__ void k_scan3(int E) {
    int t = blockIdx.x * blockDim.x + threadIdx.x;
    if (t < NNODES) {
        int o = g_off[t] + g_bpre[t >> 10];
        g_off[t] = o;
        g_cursor[t] = o;
    }
    if (t == 0) g_off[NNODES] = E;
}
__global__ void k_scatter(const int* __restrict__ ei, int E) {
    int t = blockIdx.x * blockDim.x + threadIdx.x;
    if (t < E) {
        int dst = ei[E + t];
        int pos = atomicAdd(&g_cursor[dst], 1);
        g_srcl[pos] = ei[t];
    }
}

// ======== ZU = Z @ Ucat via 3xTF32 mma ========
// BM=128, BN=64, BK=16; 8 warps as 4(M)x2(N), warp tile 32x32
__global__ __launch_bounds__(256, 1) void k_zu(const float* __restrict__ Z) {
    __shared__ float sAh[128 * 20], sAl[128 * 20];
    __shared__ float sBh[16 * 72], sBl[16 * 72];
    int tid = threadIdx.x;
    int rowBase = blockIdx.x * 128;
    int warp = tid >> 5, lane = tid & 31;
    int Mw = (warp >> 1) * 32, Nw = (warp & 1) * 32;
    int g = lane >> 2, t4 = lane & 3;

    float4 pa[2]; float4 pbh, pbl;
    // prefetch tile 0
    {
#pragma unroll
        for (int l = 0; l < 2; l++) {
            int f = tid + l * 256; int r = f >> 2, k4 = f & 3;
            int gr = rowBase + r; if (gr >= NNODES) gr = NNODES - 1;
            pa[l] = *(const float4*)&Z[gr * DDIM + k4 * 4];
        }
        int k = tid >> 4, n4 = tid & 15;
        pbh = *(const float4*)&g_Uh[k * CDIM + n4 * 4];
        pbl = *(const float4*)&g_Ul[k * CDIM + n4 * 4];
    }
    float acc[8][4];
#pragma unroll
    for (int i = 0; i < 8; i++)
#pragma unroll
        for (int j = 0; j < 4; j++) acc[i][j] = 0.f;

    for (int kt = 0; kt < 16; kt++) {
        // store prefetched tile to smem (A split on the fly)
#pragma unroll
        for (int l = 0; l < 2; l++) {
            int f = tid + l * 256; int r = f >> 2, k4 = f & 3;
            float4 v = pa[l]; float4 h, lo;
            tf_split(v.x, h.x, lo.x); tf_split(v.y, h.y, lo.y);
            tf_split(v.z, h.z, lo.z); tf_split(v.w, h.w, lo.w);
            *(float4*)&sAh[r * 20 + k4 * 4] = h;
            *(float4*)&sAl[r * 20 + k4 * 4] = lo;
        }
        {
            int k = tid >> 4, n4 = tid & 15;
            *(float4*)&sBh[k * 72 + n4 * 4] = pbh;
            *(float4*)&sBl[k * 72 + n4 * 4] = pbl;
        }
        __syncthreads();
        if (kt < 15) {
            int k0 = (kt + 1) * 16;
#pragma unroll
            for (int l = 0; l < 2; l++) {
                int f = tid + l * 256; int r = f >> 2, k4 = f & 3;
                int gr = rowBase + r; if (gr >= NNODES) gr = NNODES - 1;
                pa[l] = *(const float4*)&Z[gr * DDIM + k0 + k4 * 4];
            }
            int k = tid >> 4, n4 = tid & 15;
            pbh = *(const float4*)&g_Uh[(k0 + k) * CDIM + n4 * 4];
            pbl = *(const float4*)&g_Ul[(k0 + k) * CDIM + n4 * 4];
        }
#pragma unroll
        for (int ks = 0; ks < 2; ks++) {
            int kb = ks * 8;
            uint32_t Ah[2][4], Al[2][4], Bh[4][2], Bl[4][2];
#pragma unroll
            for (int mt = 0; mt < 2; mt++) {
                int r0 = Mw + mt * 16 + g;
                Ah[mt][0] = __float_as_uint(sAh[r0 * 20 + kb + t4]);
                Ah[mt][1] = __float_as_uint(sAh[(r0 + 8) * 20 + kb + t4]);
                Ah[mt][2] = __float_as_uint(sAh[r0 * 20 + kb + t4 + 4]);
                Ah[mt][3] = __float_as_uint(sAh[(r0 + 8) * 20 + kb + t4 + 4]);
                Al[mt][0] = __float_as_uint(sAl[r0 * 20 + kb + t4]);
                Al[mt][1] = __float_as_uint(sAl[(r0 + 8) * 20 + kb + t4]);
                Al[mt][2] = __float_as_uint(sAl[r0 * 20 + kb + t4 + 4]);
                Al[mt][3] = __float_as_uint(sAl[(r0 + 8) * 20 + kb + t4 + 4]);
            }
#pragma unroll
            for (int nt = 0; nt < 4; nt++) {
                int c0 = Nw + nt * 8 + g;
                Bh[nt][0] = __float_as_uint(sBh[(kb + t4) * 72 + c0]);
                Bh[nt][1] = __float_as_uint(sBh[(kb + t4 + 4) * 72 + c0]);
                Bl[nt][0] = __float_as_uint(sBl[(kb + t4) * 72 + c0]);
                Bl[nt][1] = __float_as_uint(sBl[(kb + t4 + 4) * 72 + c0]);
            }
#pragma unroll
            for (int mt = 0; mt < 2; mt++)
#pragma unroll
                for (int nt = 0; nt < 4; nt++) {
                    float* d = acc[mt * 4 + nt];
                    mma8(d, Ah[mt], Bh[nt]);
                    mma8(d, Ah[mt], Bl[nt]);
                    mma8(d, Al[mt], Bh[nt]);
                }
        }
        __syncthreads();
    }
#pragma unroll
    for (int mt = 0; mt < 2; mt++)
#pragma unroll
        for (int nt = 0; nt < 4; nt++) {
            int gr0 = rowBase + Mw + mt * 16 + g;
            int c = Nw + nt * 8 + 2 * t4;
            float* d = acc[mt * 4 + nt];
            if (gr0 < NNODES)     *(float2*)&g_ZU[gr0 * CDIM + c]       = make_float2(d[0], d[1]);
            if (gr0 + 8 < NNODES) *(float2*)&g_ZU[(gr0 + 8) * CDIM + c] = make_float2(d[2], d[3]);
        }
}

// ======== warp-per-node gather/softmax/aggregate ========
__global__ void k_agg() {
    int warp = (blockIdx.x * blockDim.x + threadIdx.x) >> 5;
    if (warp >= NNODES) return;
    int l = threadIdx.x & 31;
    float2 zd = *(const float2*)&g_ZU[warp * CDIM + l * 2];
    float ax = 0.f, ay = 0.f, ss = 0.f;
    int i = g_off[warp], end = g_off[warp + 1];
    for (; i + 1 < end; i += 2) {
        int s0 = g_srcl[i], s1 = g_srcl[i + 1];
        float2 a = *(const float2*)&g_ZU[s0 * CDIM + l * 2];
        float2 b = *(const float2*)&g_ZU[s1 * CDIM + l * 2];
        float p0 = a.x * zd.x + a.y * zd.y;
        float p1 = b.x * zd.x + b.y * zd.y;
        p0 += __shfl_xor_sync(0xffffffff, p0, 1);  p1 += __shfl_xor_sync(0xffffffff, p1, 1);
        p0 += __shfl_xor_sync(0xffffffff, p0, 2);  p1 += __shfl_xor_sync(0xffffffff, p1, 2);
        p0 += __shfl_xor_sync(0xffffffff, p0, 4);  p1 += __shfl_xor_sync(0xffffffff, p1, 4);
        float e0 = __expf(p0 * 0.25f), e1 = __expf(p1 * 0.25f);
        ss += e0 + e1;
        ax += e0 * a.x + e1 * b.x;
        ay += e0 * a.y + e1 * b.y;
    }
    if (i < end) {
        int s0 = g_srcl[i];
        float2 a = *(const float2*)&g_ZU[s0 * CDIM + l * 2];
        float p0 = a.x * zd.x + a.y * zd.y;
        p0 += __shfl_xor_sync(0xffffffff, p0, 1);
        p0 += __shfl_xor_sync(0xffffffff, p0, 2);
        p0 += __shfl_xor_sync(0xffffffff, p0, 4);
        float e0 = __expf(p0 * 0.25f);
        ss += e0; ax += e0 * a.x; ay += e0 * a.y;
    }
    float inv = 1.f / (ss + 1e-16f);
    *(float2*)&g_agg[warp * CDIM + l * 2] = make_float2(ax * inv, ay * inv);
}

// ======== final GEMM: out = relu([Z|Agg] @ G - 0.05) via 3xTF32 mma ========
// BM=128, BN=128, BK=16; 8 warps as 2(M)x4(N), warp tile 64x32
__global__ __launch_bounds__(256, 1) void k_final(const float* __restrict__ Z, float* __restrict__ out) {
    __shared__ float sAh[128 * 20], sAl[128 * 20];
    __shared__ float sBh[16 * 136], sBl[16 * 136];
    int tid = threadIdx.x;
    int rowBase = blockIdx.x * 128;
    int colBase = blockIdx.y * 128;
    int warp = tid >> 5, lane = tid & 31;
    int Mw = (warp >> 2) * 64, Nw = (warp & 3) * 32;
    int g = lane >> 2, t4 = lane & 3;

    float4 pa[2]; float4 pbh[2], pbl[2];
    // prefetch tile 0 (A from Z)
    {
#pragma unroll
        for (int l = 0; l < 2; l++) {
            int f = tid + l * 256; int r = f >> 2, k4 = f & 3;
            int gr = rowBase + r; if (gr >= NNODES) gr = NNODES - 1;
            pa[l] = *(const float4*)&Z[gr * DDIM + k4 * 4];
        }
#pragma unroll
        for (int l = 0; l < 2; l++) {
            int f = tid + l * 256; int k = f >> 5, n4 = f & 31;
            pbh[l] = *(const float4*)&g_Gh[k * DDIM + colBase + n4 * 4];
            pbl[l] = *(const float4*)&g_Gl[k * DDIM + colBase + n4 * 4];
        }
    }
    float acc[16][4];
#pragma unroll
    for (int i = 0; i < 16; i++)
#pragma unroll
        for (int j = 0; j < 4; j++) acc[i][j] = 0.f;

    for (int kt = 0; kt < 20; kt++) {
#pragma unroll
        for (int l = 0; l < 2; l++) {
            int f = tid + l * 256; int r = f >> 2, k4 = f & 3;
            float4 v = pa[l]; float4 h, lo;
            tf_split(v.x, h.x, lo.x); tf_split(v.y, h.y, lo.y);
            tf_split(v.z, h.z, lo.z); tf_split(v.w, h.w, lo.w);
            *(float4*)&sAh[r * 20 + k4 * 4] = h;
            *(float4*)&sAl[r * 20 + k4 * 4] = lo;
        }
#pragma unroll
        for (int l = 0; l < 2; l++) {
            int f = tid + l * 256; int k = f >> 5, n4 = f & 31;
            *(float4*)&sBh[k * 136 + n4 * 4] = pbh[l];
            *(float4*)&sBl[k * 136 + n4 * 4] = pbl[l];
        }
        __syncthreads();
        if (kt < 19) {
            int kn = kt + 1;
            const float* Aptr; int ld, koff;
            if (kn < 16) { Aptr = Z;     ld = DDIM; koff = kn * 16; }
            else         { Aptr = g_agg; ld = CDIM; koff = kn * 16 - DDIM; }
#pragma unroll
            for (int l = 0; l < 2; l++) {
                int f = tid + l * 256; int r = f >> 2, k4 = f & 3;
                int gr = rowBase + r; if (gr >= NNODES) gr = NNODES - 1;
                pa[l] = *(const float4*)&Aptr[gr * ld + koff + k4 * 4];
            }
            int kb0 = kn * 16;
#pragma unroll
            for (int l = 0; l < 2; l++) {
                int f = tid + l * 256; int k = f >> 5, n4 = f & 31;
                pbh[l] = *(const float4*)&g_Gh[(kb0 + k) * DDIM + colBase + n4 * 4];
                pbl[l] = *(const float4*)&g_Gl[(kb0 + k) * DDIM + colBase + n4 * 4];
            }
        }
#pragma unroll
        for (int ks = 0; ks < 2; ks++) {
            int kb = ks * 8;
            uint32_t Ah[4][4], Al[4][4];
#pragma unroll
            for (int mt = 0; mt < 4; mt++) {
                int r0 = Mw + mt * 16 + g;
                Ah[mt][0] = __float_as_uint(sAh[r0 * 20 + kb + t4]);
                Ah[mt][1] = __float_as_uint(sAh[(r0 + 8) * 20 + kb + t4]);
                Ah[mt][2] = __float_as_uint(sAh[r0 * 20 + kb + t4 + 4]);
                Ah[mt][3] = __float_as_uint(sAh[(r0 + 8) * 20 + kb + t4 + 4]);
                Al[mt][0] = __float_as_uint(sAl[r0 * 20 + kb + t4]);
                Al[mt][1] = __float_as_uint(sAl[(r0 + 8) * 20 + kb + t4]);
                Al[mt][2] = __float_as_uint(sAl[r0 * 20 + kb + t4 + 4]);
                Al[mt][3] = __float_as_uint(sAl[(r0 + 8) * 20 + kb + t4 + 4]);
            }
            uint32_t Bh[4][2], Bl[4][2];
#pragma unroll
            for (int nt = 0; nt < 4; nt++) {
                int c0 = Nw + nt * 8 + g;
                Bh[nt][0] = __float_as_uint(sBh[(kb + t4) * 136 + c0]);
                Bh[nt][1] = __float_as_uint(sBh[(kb + t4 + 4) * 136 + c0]);
                Bl[nt][0] = __float_as_uint(sBl[(kb + t4) * 136 + c0]);
                Bl[nt][1] = __float_as_uint(sBl[(kb + t4 + 4) * 136 + c0]);
            }
#pragma unroll
            for (int mt = 0; mt < 4; mt++)
#pragma unroll
                for (int nt = 0; nt < 4; nt++) {
                    float* d = acc[mt * 4 + nt];
                    mma8(d, Ah[mt], Bh[nt]);
                    mma8(d, Ah[mt], Bl[nt]);
                    mma8(d, Al[mt], Bh[nt]);
                }
        }
        __syncthreads();
    }
#pragma unroll
    for (int mt = 0; mt < 4; mt++)
#pragma unroll
        for (int nt = 0; nt < 4; nt++) {
            int gr0 = rowBase + Mw + mt * 16 + g;
            int c = colBase + Nw + nt * 8 + 2 * t4;
            float* d = acc[mt * 4 + nt];
            if (gr0 < NNODES)
                *(float2*)&out[gr0 * DDIM + c] =
                    make_float2(fmaxf(d[0] - 0.05f, 0.f), fmaxf(d[1] - 0.05f, 0.f));
            if (gr0 + 8 < NNODES)
                *(float2*)&out[(gr0 + 8) * DDIM + c] =
                    make_float2(fmaxf(d[2] - 0.05f, 0.f), fmaxf(d[3] - 0.05f, 0.f));
        }
}

extern "C" void kernel_launch(void* const* d_in, const int* in_sizes, int n_in,
                              void* d_out, int out_size) {
    const float* Z    = (const float*)d_in[0];
    const float* U    = (const float*)d_in[1];
    const float* Dmat = (const float*)d_in[2];
    const float* hw   = (const float*)d_in[3];
    const int*   ei   = (const int*)d_in[4];
    int E = in_sizes[4] / 2;
    float* out = (float*)d_out;

    k_prep<<<(KH * DDIM * RR + 255) / 256, 256>>>(U, hw);
    k_m1<<<dim3(8, 8), 256>>>(Dmat);
    k_m2<<<dim3(8, 8), 256>>>(Dmat);
    k_wm<<<dim3(8, 2), 256>>>();
    // CSR build
    k_cz<<<(NNODES + 255) / 256, 256>>>();
    k_hist<<<(E + 255) / 256, 256>>>(ei, E);
    k_scan1<<<NBLK_SCAN, 256>>>();
    k_scan2<<<1, 128>>>();
    k_scan3<<<(NNODES + 255) / 256, 256>>>(E);
    k_scatter<<<(E + 255) / 256, 256>>>(ei, E);
    // projections + aggregate + output
    k_zu<<<(NNODES + 127) / 128, 256>>>(Z);
    k_agg<<<(NNODES * 32 + 255) / 256, 256>>>();
    k_final<<<dim3((NNODES + 127) / 128, DDIM / 128), 256>>>(Z, out);
}

// round 8
// speedup vs baseline: 1.6415x; 1.2169x over previous
#include <cuda_runtime.h>
#include <cuda_bf16.h>
#include <cstdint>

#define NNODES 100000
#define DDIM 256
#define KH 4
#define RR 16
#define CDIM 64            // KH*RR
#define XDIM (DDIM + CDIM) // 320
#define EMAX 1700000
#define NBLK_SCAN 98       // ceil(NNODES/1024)

// -------- scratch --------
__device__ float g_ZU[NNODES * CDIM];
__device__ float g_agg[NNODES * CDIM];
__device__ float g_W[CDIM * DDIM];
__device__ float g_M1[DDIM * DDIM];
__device__ float g_M[DDIM * DDIM];
// bf16-split, transposed, pair-packed B operands
__device__ uint32_t g_UtH[CDIM * (DDIM / 2)];   // [64][128] u32, (k,k+1) bf16 pairs
__device__ uint32_t g_UtL[CDIM * (DDIM / 2)];
__device__ uint32_t g_GtH[DDIM * (XDIM / 2)];   // [256][160] u32
__device__ uint32_t g_GtL[DDIM * (XDIM / 2)];
// CSR
__device__ int g_cnt[NNODES];
__device__ int g_off[NNODES + 1];
__device__ int g_cursor[NNODES];
__device__ int g_bsum[NBLK_SCAN];
__device__ int g_bpre[NBLK_SCAN];
__device__ int g_srcl[EMAX];

// -------- bf16 helpers --------
__device__ __forceinline__ uint32_t pk(__nv_bfloat16 a, __nv_bfloat16 b) {
    __nv_bfloat162 t = __halves2bfloat162(a, b);
    return *(uint32_t*)&t;
}
__device__ __forceinline__ void bf_split(float x, __nv_bfloat16& h, __nv_bfloat16& l) {
    h = __float2bfloat16(x);
    l = __float2bfloat16(x - __bfloat162float(h));
}
// 4 consecutive floats -> 2 hi-pairs + 2 lo-pairs
__device__ __forceinline__ void split_pack4(float4 v, uint32_t& h01, uint32_t& h23,
                                            uint32_t& l01, uint32_t& l23) {
    __nv_bfloat16 hx, lx, hy, ly, hz, lz, hw, lw;
    bf_split(v.x, hx, lx); bf_split(v.y, hy, ly);
    bf_split(v.z, hz, lz); bf_split(v.w, hw, lw);
    h01 = pk(hx, hy); h23 = pk(hz, hw);
    l01 = pk(lx, ly); l23 = pk(lz, lw);
}
__device__ __forceinline__ void mma16(float* d, const uint32_t* a, const uint32_t* b) {
    asm volatile(
        "mma.sync.aligned.m16n8k16.row.col.f32.bf16.bf16.f32 "
        "{%0,%1,%2,%3},{%4,%5,%6,%7},{%8,%9},{%0,%1,%2,%3};"
        : "+f"(d[0]), "+f"(d[1]), "+f"(d[2]), "+f"(d[3])
        : "r"(a[0]), "r"(a[1]), "r"(a[2]), "r"(a[3]), "r"(b[0]), "r"(b[1]));
}

// -------- g_W (with head softmax) --------
__global__ void k_prep(const float* __restrict__ U, const float* __restrict__ hw) {
    float w0 = hw[0], w1 = hw[1], w2 = hw[2], w3 = hw[3];
    float mx = fmaxf(fmaxf(w0, w1), fmaxf(w2, w3));
    float e0 = __expf(w0 - mx), e1 = __expf(w1 - mx), e2 = __expf(w2 - mx), e3 = __expf(w3 - mx);
    float inv = 1.f / (e0 + e1 + e2 + e3);
    float wk[4] = {e0 * inv, e1 * inv, e2 * inv, e3 * inv};
    int t = blockIdx.x * blockDim.x + threadIdx.x;
    if (t < KH * DDIM * RR) {
        int k = t / (DDIM * RR);
        int d = (t / RR) % DDIM;
        int r = t % RR;
        g_W[(k * RR + r) * DDIM + d] = wk[k] * U[t];
    }
}

// -------- Ucat transposed bf16-split: g_Ut*[c][d/2] --------
__global__ void k_prepT(const float* __restrict__ U) {
    int t = blockIdx.x * blockDim.x + threadIdx.x;
    if (t >= CDIM * (DDIM / 2)) return;
    int c = t >> 7, dp = t & 127;
    int k = c >> 4, r = c & 15;
    int d = dp * 2;
    float u0 = U[(k * DDIM + d) * RR + r];
    float u1 = U[(k * DDIM + d + 1) * RR + r];
    __nv_bfloat16 h0, l0, h1, l1;
    bf_split(u0, h0, l0); bf_split(u1, h1, l1);
    g_UtH[t] = pk(h0, h1);
    g_UtL[t] = pk(l0, l1);
}

// -------- M1 = A^T A (32x32 tiles) --------
__global__ void k_m1(const float* __restrict__ A) {
    __shared__ float s1[16][33], s2[16][33];
    int tid = threadIdx.x;
    int tx = tid & 15, ty = tid >> 4;
    int i0 = blockIdx.y * 32, j0 = blockIdx.x * 32;
    float c00 = 0, c01 = 0, c10 = 0, c11 = 0;
    for (int t0 = 0; t0 < 256; t0 += 16) {
#pragma unroll
        for (int l = 0; l < 2; l++) {
            int f = tid + l * 256;
            int r = f >> 5, col = f & 31;
            s1[r][col] = A[(t0 + r) * DDIM + i0 + col];
            s2[r][col] = A[(t0 + r) * DDIM + j0 + col];
        }
        __syncthreads();
#pragma unroll
        for (int kk = 0; kk < 16; kk++) {
            float a0 = s1[kk][ty * 2], a1 = s1[kk][ty * 2 + 1];
            float b0 = s2[kk][tx * 2], b1 = s2[kk][tx * 2 + 1];
            c00 += a0 * b0; c01 += a0 * b1; c10 += a1 * b0; c11 += a1 * b1;
        }
        __syncthreads();
    }
    int i = i0 + ty * 2, j = j0 + tx * 2;
    g_M1[i * DDIM + j] = c00;       g_M1[i * DDIM + j + 1] = c01;
    g_M1[(i + 1) * DDIM + j] = c10; g_M1[(i + 1) * DDIM + j + 1] = c11;
}

// -------- M = I + 0.5*(A - M1@A); Gtop transposed split --------
__global__ void k_m2(const float* __restrict__ A) {
    __shared__ float s1[16][33], s2[16][33];
    int tid = threadIdx.x;
    int tx = tid & 15, ty = tid >> 4;
    int i0 = blockIdx.y * 32, j0 = blockIdx.x * 32;
    float c00 = 0, c01 = 0, c10 = 0, c11 = 0;
    for (int t0 = 0; t0 < 256; t0 += 16) {
#pragma unroll
        for (int l = 0; l < 2; l++) {
            int f = tid + l * 256;
            int tt = f & 15, ii = f >> 4;
            s1[tt][ii] = g_M1[(i0 + ii) * DDIM + t0 + tt];
            int r = f >> 5, col = f & 31;
            s2[r][col] = A[(t0 + r) * DDIM + j0 + col];
        }
        __syncthreads();
#pragma unroll
        for (int kk = 0; kk < 16; kk++) {
            float a0 = s1[kk][ty * 2], a1 = s1[kk][ty * 2 + 1];
            float b0 = s2[kk][tx * 2], b1 = s2[kk][tx * 2 + 1];
            c00 += a0 * b0; c01 += a0 * b1; c10 += a1 * b0; c11 += a1 * b1;
        }
        __syncthreads();
    }
    int i = i0 + ty * 2, j = j0 + tx * 2;
    float m00 = ((i == j)         ? 1.f : 0.f) + 0.5f * (A[i * DDIM + j]           - c00);
    float m01 = ((i == j + 1)     ? 1.f : 0.f) + 0.5f * (A[i * DDIM + j + 1]       - c01);
    float m10 = ((i + 1 == j)     ? 1.f : 0.f) + 0.5f * (A[(i + 1) * DDIM + j]     - c10);
    float m11 = ((i + 1 == j + 1) ? 1.f : 0.f) + 0.5f * (A[(i + 1) * DDIM + j + 1] - c11);
    g_M[i * DDIM + j] = m00;       g_M[i * DDIM + j + 1] = m01;
    g_M[(i + 1) * DDIM + j] = m10; g_M[(i + 1) * DDIM + j + 1] = m11;
    // Gtop = 0.5*M, transposed [j][i], (i,i+1) pair packed
    __nv_bfloat16 h0, l0, h1, l1;
    bf_split(0.5f * m00, h0, l0); bf_split(0.5f * m10, h1, l1);
    g_GtH[j * (XDIM / 2) + (i >> 1)] = pk(h0, h1);
    g_GtL[j * (XDIM / 2) + (i >> 1)] = pk(l0, l1);
    bf_split(0.5f * m01, h0, l0); bf_split(0.5f * m11, h1, l1);
    g_GtH[(j + 1) * (XDIM / 2) + (i >> 1)] = pk(h0, h1);
    g_GtL[(j + 1) * (XDIM / 2) + (i >> 1)] = pk(l0, l1);
}

// -------- Gbot = 0.5 * (W @ M), transposed split --------
__global__ void k_wm() {
    __shared__ float s1[16][33], s2[16][33];
    int tid = threadIdx.x;
    int tx = tid & 15, ty = tid >> 4;
    int i0 = blockIdx.y * 32, j0 = blockIdx.x * 32;
    float c00 = 0, c01 = 0, c10 = 0, c11 = 0;
    for (int t0 = 0; t0 < 256; t0 += 16) {
#pragma unroll
        for (int l = 0; l < 2; l++) {
            int f = tid + l * 256;
            int tt = f & 15, ii = f >> 4;
            s1[tt][ii] = g_W[(i0 + ii) * DDIM + t0 + tt];
            int r = f >> 5, col = f & 31;
            s2[r][col] = g_M[(t0 + r) * DDIM + j0 + col];
        }
        __syncthreads();
#pragma unroll
        for (int kk = 0; kk < 16; kk++) {
            float a0 = s1[kk][ty * 2], a1 = s1[kk][ty * 2 + 1];
            float b0 = s2[kk][tx * 2], b1 = s2[kk][tx * 2 + 1];
            c00 += a0 * b0; c01 += a0 * b1; c10 += a1 * b0; c11 += a1 * b1;
        }
        __syncthreads();
    }
    int i = i0 + ty * 2, j = j0 + tx * 2;   // rows DDIM+i of G
    __nv_bfloat16 h0, l0, h1, l1;
    bf_split(0.5f * c00, h0, l0); bf_split(0.5f * c10, h1, l1);
    g_GtH[j * (XDIM / 2) + 128 + (i >> 1)] = pk(h0, h1);
    g_GtL[j * (XDIM / 2) + 128 + (i >> 1)] = pk(l0, l1);
    bf_split(0.5f * c01, h0, l0); bf_split(0.5f * c11, h1, l1);
    g_GtH[(j + 1) * (XDIM / 2) + 128 + (i >> 1)] = pk(h0, h1);
    g_GtL[(j + 1) * (XDIM / 2) + 128 + (i >> 1)] = pk(l0, l1);
}

// ======== CSR build ========
__global__ void k_cz() {
    int t = blockIdx.x * blockDim.x + threadIdx.x;
    if (t < NNODES) g_cnt[t] = 0;
}
__global__ void k_hist(const int* __restrict__ ei, int E) {
    int t = blockIdx.x * blockDim.x + threadIdx.x;
    if (t < E) atomicAdd(&g_cnt[ei[E + t]], 1);
}
__global__ void k_scan1() {
    __shared__ int s_warp[8];
    int b = blockIdx.x, t = threadIdx.x;
    int base = b * 1024 + t * 4;
    int v[4];
#pragma unroll
    for (int i = 0; i < 4; i++) { int idx = base + i; v[i] = (idx < NNODES) ? g_cnt[idx] : 0; }
    int sum = v[0] + v[1] + v[2] + v[3];
    int lane = t & 31, wid = t >> 5;
    int x = sum;
#pragma unroll
    for (int o = 1; o < 32; o <<= 1) { int y = __shfl_up_sync(0xffffffff, x, o); if (lane >= o) x += y; }
    if (lane == 31) s_warp[wid] = x;
    __syncthreads();
    if (wid == 0) {
        int w = (lane < 8) ? s_warp[lane] : 0;
#pragma unroll
        for (int o = 1; o < 8; o <<= 1) { int y = __shfl_up_sync(0xffffffff, w, o); if (lane >= o) w += y; }
        if (lane < 8) s_warp[lane] = w;
    }
    __syncthreads();
    int warppre = (wid > 0) ? s_warp[wid - 1] : 0;
    int run = warppre + x - sum;
#pragma unroll
    for (int i = 0; i < 4; i++) { int idx = base + i; if (idx < NNODES) g_off[idx] = run; run += v[i]; }
    if (t == 255) g_bsum[b] = warppre + x;
}
__global__ void k_scan2() {
    __shared__ int sw[4];
    int t = threadIdx.x;
    int v = (t < NBLK_SCAN) ? g_bsum[t] : 0;
    int lane = t & 31, wid = t >> 5;
    int x = v;
#pragma unroll
    for (int o = 1; o < 32; o <<= 1) { int y = __shfl_up_sync(0xffffffff, x, o); if (lane >= o) x += y; }
    if (lane == 31) sw[wid] = x;
    __syncthreads();
    if (t == 0) { int a = 0; for (int i = 0; i < 4; i++) { int tmp = sw[i]; sw[i] = a; a += tmp; } }
    __syncthreads();
    if (t < NBLK_SCAN) g_bpre[t] = sw[wid] + x - v;
}
__global__ void k_scan3(int E) {
    int t = blockIdx.x * blockDim.x + threadIdx.x;
    if (t < NNODES) {
        int o = g_off[t] + g_bpre[t >> 10];
        g_off[t] = o;
        g_cursor[t] = o;
    }
    if (t == 0) g_off[NNODES] = E;
}
__global__ void k_scatter(const int* __restrict__ ei, int E) {
    int t = blockIdx.x * blockDim.x + threadIdx.x;
    if (t < E) {
        int dst = ei[E + t];
        int pos = atomicAdd(&g_cursor[dst], 1);
        g_srcl[pos] = ei[t];
    }
}

// ======== ZU = Z @ Ucat via bf16-split mma (m16n8k16) ========
// BM=128, BN=64, BK=16; 8 warps 4(M)x2(N), warp tile 32x32
__global__ __launch_bounds__(256, 1) void k_zu(const float* __restrict__ Z) {
    __shared__ uint32_t sAh[128 * 12], sAl[128 * 12];   // rows x (8 data + 4 pad) u32
    __shared__ uint32_t sBh[64 * 12], sBl[64 * 12];
    int tid = threadIdx.x;
    int rowBase = blockIdx.x * 128;
    int warp = tid >> 5, lane = tid & 31;
    int Mw = (warp >> 1) * 32, Nw = (warp & 1) * 32;
    int g = lane >> 2, t4 = lane & 3;

    float4 pa[2]; uint2 pbh, pbl;
    {
#pragma unroll
        for (int l = 0; l < 2; l++) {
            int f = tid + l * 256; int r = f >> 2, k4 = f & 3;
            int gr = rowBase + r; if (gr >= NNODES) gr = NNODES - 1;
            pa[l] = *(const float4*)&Z[gr * DDIM + k4 * 4];
        }
        int n = tid >> 2, kk2 = tid & 3;
        pbh = *(const uint2*)&g_UtH[n * (DDIM / 2) + kk2 * 2];
        pbl = *(const uint2*)&g_UtL[n * (DDIM / 2) + kk2 * 2];
    }
    float acc[8][4];
#pragma unroll
    for (int i = 0; i < 8; i++)
#pragma unroll
        for (int j = 0; j < 4; j++) acc[i][j] = 0.f;

    for (int kt = 0; kt < 16; kt++) {
#pragma unroll
        for (int l = 0; l < 2; l++) {
            int f = tid + l * 256; int r = f >> 2, k4 = f & 3;
            uint32_t h01, h23, l01, l23;
            split_pack4(pa[l], h01, h23, l01, l23);
            sAh[r * 12 + k4 * 2] = h01; sAh[r * 12 + k4 * 2 + 1] = h23;
            sAl[r * 12 + k4 * 2] = l01; sAl[r * 12 + k4 * 2 + 1] = l23;
        }
        {
            int n = tid >> 2, kk2 = tid & 3;
            *(uint2*)&sBh[n * 12 + kk2 * 2] = pbh;
            *(uint2*)&sBl[n * 12 + kk2 * 2] = pbl;
        }
        __syncthreads();
        if (kt < 15) {
            int k0 = (kt + 1) * 16;
#pragma unroll
            for (int l = 0; l < 2; l++) {
                int f = tid + l * 256; int r = f >> 2, k4 = f & 3;
                int gr = rowBase + r; if (gr >= NNODES) gr = NNODES - 1;
                pa[l] = *(const float4*)&Z[gr * DDIM + k0 + k4 * 4];
            }
            int n = tid >> 2, kk2 = tid & 3;
            pbh = *(const uint2*)&g_UtH[n * (DDIM / 2) + k0 / 2 + kk2 * 2];
            pbl = *(const uint2*)&g_UtL[n * (DDIM / 2) + k0 / 2 + kk2 * 2];
        }
        uint32_t Ah[2][4], Al[2][4], Bh[4][2], Bl[4][2];
#pragma unroll
        for (int mt = 0; mt < 2; mt++) {
            int r0 = Mw + mt * 16 + g;
            Ah[mt][0] = sAh[r0 * 12 + t4];       Ah[mt][1] = sAh[(r0 + 8) * 12 + t4];
            Ah[mt][2] = sAh[r0 * 12 + 4 + t4];   Ah[mt][3] = sAh[(r0 + 8) * 12 + 4 + t4];
            Al[mt][0] = sAl[r0 * 12 + t4];       Al[mt][1] = sAl[(r0 + 8) * 12 + t4];
            Al[mt][2] = sAl[r0 * 12 + 4 + t4];   Al[mt][3] = sAl[(r0 + 8) * 12 + 4 + t4];
        }
#pragma unroll
        for (int nt = 0; nt < 4; nt++) {
            int c0 = Nw + nt * 8 + g;
            Bh[nt][0] = sBh[c0 * 12 + t4];  Bh[nt][1] = sBh[c0 * 12 + 4 + t4];
            Bl[nt][0] = sBl[c0 * 12 + t4];  Bl[nt][1] = sBl[c0 * 12 + 4 + t4];
        }
#pragma unroll
        for (int mt = 0; mt < 2; mt++)
#pragma unroll
            for (int nt = 0; nt < 4; nt++) {
                float* d = acc[mt * 4 + nt];
                mma16(d, Ah[mt], Bh[nt]);
                mma16(d, Ah[mt], Bl[nt]);
                mma16(d, Al[mt], Bh[nt]);
            }
        __syncthreads();
    }
#pragma unroll
    for (int mt = 0; mt < 2; mt++)
#pragma unroll
        for (int nt = 0; nt < 4; nt++) {
            int gr0 = rowBase + Mw + mt * 16 + g;
            int c = Nw + nt * 8 + 2 * t4;
            float* d = acc[mt * 4 + nt];
            if (gr0 < NNODES)     *(float2*)&g_ZU[gr0 * CDIM + c]       = make_float2(d[0], d[1]);
            if (gr0 + 8 < NNODES) *(float2*)&g_ZU[(gr0 + 8) * CDIM + c] = make_float2(d[2], d[3]);
        }
}

// ======== warp-per-node gather/softmax/aggregate ========
__global__ void k_agg() {
    int warp = (blockIdx.x * blockDim.x + threadIdx.x) >> 5;
    if (warp >= NNODES) return;
    int l = threadIdx.x & 31;
    float2 zd = *(const float2*)&g_ZU[warp * CDIM + l * 2];
    float ax = 0.f, ay = 0.f, ss = 0.f;
    int i = g_off[warp], end = g_off[warp + 1];
    for (; i + 1 < end; i += 2) {
        int s0 = g_srcl[i], s1 = g_srcl[i + 1];
        float2 a = *(const float2*)&g_ZU[s0 * CDIM + l * 2];
        float2 b = *(const float2*)&g_ZU[s1 * CDIM + l * 2];
        float p0 = a.x * zd.x + a.y * zd.y;
        float p1 = b.x * zd.x + b.y * zd.y;
        p0 += __shfl_xor_sync(0xffffffff, p0, 1);  p1 += __shfl_xor_sync(0xffffffff, p1, 1);
        p0 += __shfl_xor_sync(0xffffffff, p0, 2);  p1 += __shfl_xor_sync(0xffffffff, p1, 2);
        p0 += __shfl_xor_sync(0xffffffff, p0, 4);  p1 += __shfl_xor_sync(0xffffffff, p1, 4);
        float e0 = __expf(p0 * 0.25f), e1 = __expf(p1 * 0.25f);
        ss += e0 + e1;
        ax += e0 * a.x + e1 * b.x;
        ay += e0 * a.y + e1 * b.y;
    }
    if (i < end) {
        int s0 = g_srcl[i];
        float2 a = *(const float2*)&g_ZU[s0 * CDIM + l * 2];
        float p0 = a.x * zd.x + a.y * zd.y;
        p0 += __shfl_xor_sync(0xffffffff, p0, 1);
        p0 += __shfl_xor_sync(0xffffffff, p0, 2);
        p0 += __shfl_xor_sync(0xffffffff, p0, 4);
        float e0 = __expf(p0 * 0.25f);
        ss += e0; ax += e0 * a.x; ay += e0 * a.y;
    }
    float inv = 1.f / (ss + 1e-16f);
    *(float2*)&g_agg[warp * CDIM + l * 2] = make_float2(ax * inv, ay * inv);
}

// ======== final GEMM: out = relu([Z|Agg] @ G - 0.05) via bf16-split mma ========
// BM=128, BN=128, BK=16; 8 warps 2(M)x4(N), warp tile 64x32
__global__ __launch_bounds__(256, 1) void k_final(const float* __restrict__ Z, float* __restrict__ out) {
    __shared__ uint32_t sAh[128 * 12], sAl[128 * 12];
    __shared__ uint32_t sBh[128 * 12], sBl[128 * 12];
    int tid = threadIdx.x;
    int rowBase = blockIdx.x * 128;
    int colBase = blockIdx.y * 128;
    int warp = tid >> 5, lane = tid & 31;
    int Mw = (warp >> 2) * 64, Nw = (warp & 3) * 32;
    int g = lane >> 2, t4 = lane & 3;

    float4 pa[2]; uint2 pbh[2], pbl[2];
    {
#pragma unroll
        for (int l = 0; l < 2; l++) {
            int f = tid + l * 256; int r = f >> 2, k4 = f & 3;
            int gr = rowBase + r; if (gr >= NNODES) gr = NNODES - 1;
            pa[l] = *(const float4*)&Z[gr * DDIM + k4 * 4];
        }
#pragma unroll
        for (int l = 0; l < 2; l++) {
            int f = tid + l * 256; int n = f >> 2, kk2 = f & 3;
            pbh[l] = *(const uint2*)&g_GtH[(colBase + n) * (XDIM / 2) + kk2 * 2];
            pbl[l] = *(const uint2*)&g_GtL[(colBase + n) * (XDIM / 2) + kk2 * 2];
        }
    }
    float acc[16][4];
#pragma unroll
    for (int i = 0; i < 16; i++)
#pragma unroll
        for (int j = 0; j < 4; j++) acc[i][j] = 0.f;

    for (int kt = 0; kt < 20; kt++) {
#pragma unroll
        for (int l = 0; l < 2; l++) {
            int f = tid + l * 256; int r = f >> 2, k4 = f & 3;
            uint32_t h01, h23, l01, l23;
            split_pack4(pa[l], h01, h23, l01, l23);
            sAh[r * 12 + k4 * 2] = h01; sAh[r * 12 + k4 * 2 + 1] = h23;
            sAl[r * 12 + k4 * 2] = l01; sAl[r * 12 + k4 * 2 + 1] = l23;
        }
#pragma unroll
        for (int l = 0; l < 2; l++) {
            int f = tid + l * 256; int n = f >> 2, kk2 = f & 3;
            *(uint2*)&sBh[n * 12 + kk2 * 2] = pbh[l];
            *(uint2*)&sBl[n * 12 + kk2 * 2] = pbl[l];
        }
        __syncthreads();
        if (kt < 19) {
            int kn = kt + 1;
            const float* Aptr; int ld, koff;
            if (kn < 16) { Aptr = Z;     ld = DDIM; koff = kn * 16; }
            else         { Aptr = g_agg; ld = CDIM; koff = kn * 16 - DDIM; }
#pragma unroll
            for (int l = 0; l < 2; l++) {
                int f = tid + l * 256; int r = f >> 2, k4 = f & 3;
                int gr = rowBase + r; if (gr >= NNODES) gr = NNODES - 1;
                pa[l] = *(const float4*)&Aptr[gr * ld + koff + k4 * 4];
            }
#pragma unroll
            for (int l = 0; l < 2; l++) {
                int f = tid + l * 256; int n = f >> 2, kk2 = f & 3;
                pbh[l] = *(const uint2*)&g_GtH[(colBase + n) * (XDIM / 2) + kn * 8 + kk2 * 2];
                pbl[l] = *(const uint2*)&g_GtL[(colBase + n) * (XDIM / 2) + kn * 8 + kk2 * 2];
            }
        }
        uint32_t Ah[4][4], Al[4][4], Bh[4][2], Bl[4][2];
#pragma unroll
        for (int mt = 0; mt < 4; mt++) {
            int r0 = Mw + mt * 16 + g;
            Ah[mt][0] = sAh[r0 * 12 + t4];       Ah[mt][1] = sAh[(r0 + 8) * 12 + t4];
            Ah[mt][2] = sAh[r0 * 12 + 4 + t4];   Ah[mt][3] = sAh[(r0 + 8) * 12 + 4 + t4];
            Al[mt][0] = sAl[r0 * 12 + t4];       Al[mt][1] = sAl[(r0 + 8) * 12 + t4];
            Al[mt][2] = sAl[r0 * 12 + 4 + t4];   Al[mt][3] = sAl[(r0 + 8) * 12 + 4 + t4];
        }
#pragma unroll
        for (int nt = 0; nt < 4; nt++) {
            int c0 = Nw + nt * 8 + g;
            Bh[nt][0] = sBh[c0 * 12 + t4];  Bh[nt][1] = sBh[c0 * 12 + 4 + t4];
            Bl[nt][0] = sBl[c0 * 12 + t4];  Bl[nt][1] = sBl[c0 * 12 + 4 + t4];
        }
#pragma unroll
        for (int mt = 0; mt < 4; mt++)
#pragma unroll
            for (int nt = 0; nt < 4; nt++) {
                float* d = acc[mt * 4 + nt];
                mma16(d, Ah[mt], Bh[nt]);
                mma16(d, Ah[mt], Bl[nt]);
                mma16(d, Al[mt], Bh[nt]);
            }
        __syncthreads();
    }
#pragma unroll
    for (int mt = 0; mt < 4; mt++)
#pragma unroll
        for (int nt = 0; nt < 4; nt++) {
            int gr0 = rowBase + Mw + mt * 16 + g;
            int c = colBase + Nw + nt * 8 + 2 * t4;
            float* d = acc[mt * 4 + nt];
            if (gr0 < NNODES)
                *(float2*)&out[gr0 * DDIM + c] =
                    make_float2(fmaxf(d[0] - 0.05f, 0.f), fmaxf(d[1] - 0.05f, 0.f));
            if (gr0 + 8 < NNODES)
                *(float2*)&out[(gr0 + 8) * DDIM + c] =
                    make_float2(fmaxf(d[2] - 0.05f, 0.f), fmaxf(d[3] - 0.05f, 0.f));
        }
}

extern "C" void kernel_launch(void* const* d_in, const int* in_sizes, int n_in,
                              void* d_out, int out_size) {
    const float* Z    = (const float*)d_in[0];
    const float* U    = (const float*)d_in[1];
    const float* Dmat = (const float*)d_in[2];
    const float* hw   = (const float*)d_in[3];
    const int*   ei   = (const int*)d_in[4];
    int E = in_sizes[4] / 2;
    float* out = (float*)d_out;

    k_prep<<<(KH * DDIM * RR + 255) / 256, 256>>>(U, hw);
    k_prepT<<<(CDIM * (DDIM / 2) + 255) / 256, 256>>>(U);
    k_m1<<<dim3(8, 8), 256>>>(Dmat);
    k_m2<<<dim3(8, 8), 256>>>(Dmat);
    k_wm<<<dim3(8, 2), 256>>>();
    // CSR build
    k_cz<<<(NNODES + 255) / 256, 256>>>();
    k_hist<<<(E + 255) / 256, 256>>>(ei, E);
    k_scan1<<<NBLK_SCAN, 256>>>();
    k_scan2<<<1, 128>>>();
    k_scan3<<<(NNODES + 255) / 256, 256>>>(E);
    k_scatter<<<(E + 255) / 256, 256>>>(ei, E);
    // projections + aggregate + output
    k_zu<<<(NNODES + 127) / 128, 256>>>(Z);
    k_agg<<<(NNODES * 32 + 255) / 256, 256>>>();
    k_final<<<dim3((NNODES + 127) / 128, DDIM / 128), 256>>>(Z, out);
}

// round 15
// speedup vs baseline: 1.7458x; 1.0636x over previous
#include <cuda_runtime.h>
#include <cuda_bf16.h>
#include <cstdint>

#define NNODES 100000
#define DDIM 256
#define KH 4
#define RR 16
#define CDIM 64            // KH*RR
#define XDIM (DDIM + CDIM) // 320
#define EMAX 1700000
#define NBLK_SCAN 98       // ceil(NNODES/1024)

// -------- scratch --------
__device__ float g_ZU[NNODES * CDIM];
__device__ float g_agg[NNODES * CDIM];
__device__ float g_W[CDIM * DDIM];
__device__ float g_M1[DDIM * DDIM];
__device__ float g_M[DDIM * DDIM];
__device__ uint32_t g_UtH[CDIM * (DDIM / 2)];
__device__ uint32_t g_UtL[CDIM * (DDIM / 2)];
__device__ uint32_t g_GtH[DDIM * (XDIM / 2)];   // [n][k-pair] packed bf16 hi
__device__ uint32_t g_GtL[DDIM * (XDIM / 2)];
// CSR
__device__ int g_cnt[NNODES];
__device__ int g_off[NNODES + 1];
__device__ int g_cursor[NNODES];
__device__ int g_bsum[NBLK_SCAN];
__device__ int g_bpre[NBLK_SCAN];
__device__ int g_srcl[EMAX];

// -------- bf16 helpers --------
__device__ __forceinline__ uint32_t pk(__nv_bfloat16 a, __nv_bfloat16 b) {
    __nv_bfloat162 t = __halves2bfloat162(a, b);
    return *(uint32_t*)&t;
}
__device__ __forceinline__ void bf_split(float x, __nv_bfloat16& h, __nv_bfloat16& l) {
    h = __float2bfloat16(x);
    l = __float2bfloat16(x - __bfloat162float(h));
}
__device__ __forceinline__ void split_pack4(float4 v, uint32_t& h01, uint32_t& h23,
                                            uint32_t& l01, uint32_t& l23) {
    __nv_bfloat16 hx, lx, hy, ly, hz, lz, hw, lw;
    bf_split(v.x, hx, lx); bf_split(v.y, hy, ly);
    bf_split(v.z, hz, lz); bf_split(v.w, hw, lw);
    h01 = pk(hx, hy); h23 = pk(hz, hw);
    l01 = pk(lx, ly); l23 = pk(lz, lw);
}
__device__ __forceinline__ void mma16(float* d, const uint32_t* a, const uint32_t* b) {
    asm volatile(
        "mma.sync.aligned.m16n8k16.row.col.f32.bf16.bf16.f32 "
        "{%0,%1,%2,%3},{%4,%5,%6,%7},{%8,%9},{%0,%1,%2,%3};"
        : "+f"(d[0]), "+f"(d[1]), "+f"(d[2]), "+f"(d[3])
        : "r"(a[0]), "r"(a[1]), "r"(a[2]), "r"(a[3]), "r"(b[0]), "r"(b[1]));
}

// ================= device bodies (bid-parameterized) =================

__device__ void d_prep(int bid, const float* __restrict__ U, const float* __restrict__ hw) {
    float w0 = hw[0], w1 = hw[1], w2 = hw[2], w3 = hw[3];
    float mx = fmaxf(fmaxf(w0, w1), fmaxf(w2, w3));
    float e0 = __expf(w0 - mx), e1 = __expf(w1 - mx), e2 = __expf(w2 - mx), e3 = __expf(w3 - mx);
    float inv = 1.f / (e0 + e1 + e2 + e3);
    float wk[4] = {e0 * inv, e1 * inv, e2 * inv, e3 * inv};
    int t = bid * 256 + threadIdx.x;
    if (t < KH * DDIM * RR) {
        int k = t / (DDIM * RR);
        int d = (t / RR) % DDIM;
        int r = t % RR;
        g_W[(k * RR + r) * DDIM + d] = wk[k] * U[t];
    }
}

__device__ void d_prepT(int bid, const float* __restrict__ U) {
    int t = bid * 256 + threadIdx.x;
    if (t >= CDIM * (DDIM / 2)) return;
    int c = t >> 7, dp = t & 127;
    int k = c >> 4, r = c & 15;
    int d = dp * 2;
    float u0 = U[(k * DDIM + d) * RR + r];
    float u1 = U[(k * DDIM + d + 1) * RR + r];
    __nv_bfloat16 h0, l0, h1, l1;
    bf_split(u0, h0, l0); bf_split(u1, h1, l1);
    g_UtH[t] = pk(h0, h1);
    g_UtL[t] = pk(l0, l1);
}

__device__ void d_hist(int bid, const int* __restrict__ ei, int E) {
    int t = bid * 256 + threadIdx.x;
    if (t < E) atomicAdd(&g_cnt[ei[E + t]], 1);
}

struct SM_M { float s1[16][33]; float s2[16][33]; };

__device__ void d_m1(int bid, const float* __restrict__ A, SM_M* sm) {
    int tid = threadIdx.x;
    int tx = tid & 15, ty = tid >> 4;
    int i0 = (bid >> 3) * 32, j0 = (bid & 7) * 32;
    float c00 = 0, c01 = 0, c10 = 0, c11 = 0;
    for (int t0 = 0; t0 < 256; t0 += 16) {
#pragma unroll
        for (int l = 0; l < 2; l++) {
            int f = tid + l * 256;
            int r = f >> 5, col = f & 31;
            sm->s1[r][col] = A[(t0 + r) * DDIM + i0 + col];
            sm->s2[r][col] = A[(t0 + r) * DDIM + j0 + col];
        }
        __syncthreads();
#pragma unroll
        for (int kk = 0; kk < 16; kk++) {
            float a0 = sm->s1[kk][ty * 2], a1 = sm->s1[kk][ty * 2 + 1];
            float b0 = sm->s2[kk][tx * 2], b1 = sm->s2[kk][tx * 2 + 1];
            c00 += a0 * b0; c01 += a0 * b1; c10 += a1 * b0; c11 += a1 * b1;
        }
        __syncthreads();
    }
    int i = i0 + ty * 2, j = j0 + tx * 2;
    g_M1[i * DDIM + j] = c00;       g_M1[i * DDIM + j + 1] = c01;
    g_M1[(i + 1) * DDIM + j] = c10; g_M1[(i + 1) * DDIM + j + 1] = c11;
}

__device__ void d_m2(int bid, const float* __restrict__ A, SM_M* sm) {
    int tid = threadIdx.x;
    int tx = tid & 15, ty = tid >> 4;
    int i0 = (bid >> 3) * 32, j0 = (bid & 7) * 32;
    float c00 = 0, c01 = 0, c10 = 0, c11 = 0;
    for (int t0 = 0; t0 < 256; t0 += 16) {
#pragma unroll
        for (int l = 0; l < 2; l++) {
            int f = tid + l * 256;
            int tt = f & 15, ii = f >> 4;
            sm->s1[tt][ii] = g_M1[(i0 + ii) * DDIM + t0 + tt];
            int r = f >> 5, col = f & 31;
            sm->s2[r][col] = A[(t0 + r) * DDIM + j0 + col];
        }
        __syncthreads();
#pragma unroll
        for (int kk = 0; kk < 16; kk++) {
            float a0 = sm->s1[kk][ty * 2], a1 = sm->s1[kk][ty * 2 + 1];
            float b0 = sm->s2[kk][tx * 2], b1 = sm->s2[kk][tx * 2 + 1];
            c00 += a0 * b0; c01 += a0 * b1; c10 += a1 * b0; c11 += a1 * b1;
        }
        __syncthreads();
    }
    int i = i0 + ty * 2, j = j0 + tx * 2;
    float mm[2][2];
    mm[0][0] = ((i == j)         ? 1.f : 0.f) + 0.5f * (A[i * DDIM + j]           - c00);
    mm[0][1] = ((i == j + 1)     ? 1.f : 0.f) + 0.5f * (A[i * DDIM + j + 1]       - c01);
    mm[1][0] = ((i + 1 == j)     ? 1.f : 0.f) + 0.5f * (A[(i + 1) * DDIM + j]     - c10);
    mm[1][1] = ((i + 1 == j + 1) ? 1.f : 0.f) + 0.5f * (A[(i + 1) * DDIM + j + 1] - c11);
#pragma unroll
    for (int a = 0; a < 2; a++)
#pragma unroll
        for (int b = 0; b < 2; b++) {
            int ii = i + a, jj = j + b;
            g_M[ii * DDIM + jj] = mm[a][b];
        }
    // Gtop = 0.5*M, transposed [j][i], (i,i+1) pair packed
    __nv_bfloat16 h0, l0, h1, l1;
    bf_split(0.5f * mm[0][0], h0, l0); bf_split(0.5f * mm[1][0], h1, l1);
    g_GtH[j * (XDIM / 2) + (i >> 1)] = pk(h0, h1);
    g_GtL[j * (XDIM / 2) + (i >> 1)] = pk(l0, l1);
    bf_split(0.5f * mm[0][1], h0, l0); bf_split(0.5f * mm[1][1], h1, l1);
    g_GtH[(j + 1) * (XDIM / 2) + (i >> 1)] = pk(h0, h1);
    g_GtL[(j + 1) * (XDIM / 2) + (i >> 1)] = pk(l0, l1);
}

__device__ void d_wm(int bid, SM_M* sm) {
    int tid = threadIdx.x;
    int tx = tid & 15, ty = tid >> 4;
    int i0 = (bid >> 3) * 32, j0 = (bid & 7) * 32;
    float c00 = 0, c01 = 0, c10 = 0, c11 = 0;
    for (int t0 = 0; t0 < 256; t0 += 16) {
#pragma unroll
        for (int l = 0; l < 2; l++) {
            int f = tid + l * 256;
            int tt = f & 15, ii = f >> 4;
            sm->s1[tt][ii] = g_W[(i0 + ii) * DDIM + t0 + tt];
            int r = f >> 5, col = f & 31;
            sm->s2[r][col] = g_M[(t0 + r) * DDIM + j0 + col];
        }
        __syncthreads();
#pragma unroll
        for (int kk = 0; kk < 16; kk++) {
            float a0 = sm->s1[kk][ty * 2], a1 = sm->s1[kk][ty * 2 + 1];
            float b0 = sm->s2[kk][tx * 2], b1 = sm->s2[kk][tx * 2 + 1];
            c00 += a0 * b0; c01 += a0 * b1; c10 += a1 * b0; c11 += a1 * b1;
        }
        __syncthreads();
    }
    int i = i0 + ty * 2, j = j0 + tx * 2;
    float cc[2][2] = {{c00, c01}, {c10, c11}};
    __nv_bfloat16 h0, l0, h1, l1;
    bf_split(0.5f * cc[0][0], h0, l0); bf_split(0.5f * cc[1][0], h1, l1);
    g_GtH[j * (XDIM / 2) + 128 + (i >> 1)] = pk(h0, h1);
    g_GtL[j * (XDIM / 2) + 128 + (i >> 1)] = pk(l0, l1);
    bf_split(0.5f * cc[0][1], h0, l0); bf_split(0.5f * cc[1][1], h1, l1);
    g_GtH[(j + 1) * (XDIM / 2) + 128 + (i >> 1)] = pk(h0, h1);
    g_GtL[(j + 1) * (XDIM / 2) + 128 + (i >> 1)] = pk(l0, l1);
}

__device__ void d_scan1(int b, int* s_warp) {
    int t = threadIdx.x;
    int base = b * 1024 + t * 4;
    int v[4];
#pragma unroll
    for (int i = 0; i < 4; i++) { int idx = base + i; v[i] = (idx < NNODES) ? g_cnt[idx] : 0; }
    int sum = v[0] + v[1] + v[2] + v[3];
    int lane = t & 31, wid = t >> 5;
    int x = sum;
#pragma unroll
    for (int o = 1; o < 32; o <<= 1) { int y = __shfl_up_sync(0xffffffff, x, o); if (lane >= o) x += y; }
    if (lane == 31) s_warp[wid] = x;
    __syncthreads();
    if (wid == 0) {
        int w = (lane < 8) ? s_warp[lane] : 0;
#pragma unroll
        for (int o = 1; o < 8; o <<= 1) { int y = __shfl_up_sync(0xffffffff, w, o); if (lane >= o) w += y; }
        if (lane < 8) s_warp[lane] = w;
    }
    __syncthreads();
    int warppre = (wid > 0) ? s_warp[wid - 1] : 0;
    int run = warppre + x - sum;
#pragma unroll
    for (int i = 0; i < 4; i++) { int idx = base + i; if (idx < NNODES) g_off[idx] = run; run += v[i]; }
    if (t == 255) g_bsum[b] = warppre + x;
}

__device__ void d_scan2(int* sw) {
    int t = threadIdx.x;
    if (t >= 128) { __syncthreads(); __syncthreads(); return; }
    int v = (t < NBLK_SCAN) ? g_bsum[t] : 0;
    int lane = t & 31, wid = t >> 5;
    int x = v;
#pragma unroll
    for (int o = 1; o < 32; o <<= 1) { int y = __shfl_up_sync(0xffffffff, x, o); if (lane >= o) x += y; }
    if (lane == 31) sw[wid] = x;
    __syncthreads();
    if (t == 0) { int a = 0; for (int i = 0; i < 4; i++) { int tmp = sw[i]; sw[i] = a; a += tmp; } }
    __syncthreads();
    if (t < NBLK_SCAN) g_bpre[t] = sw[wid] + x - v;
}

__device__ void d_scan3(int bid, int E) {
    int t = bid * 256 + threadIdx.x;
    if (t < NNODES) {
        int o = g_off[t] + g_bpre[t >> 10];
        g_off[t] = o;
        g_cursor[t] = o;
    }
    if (t == 0) g_off[NNODES] = E;
}

struct SM_ZU {
    uint32_t sAh[128 * 12]; uint32_t sAl[128 * 12];
    uint32_t sBh[64 * 12];  uint32_t sBl[64 * 12];
};

__device__ void d_zu(int zbid, const float* __restrict__ Z, SM_ZU* sm) {
    int tid = threadIdx.x;
    int rowBase = zbid * 128;
    int warp = tid >> 5, lane = tid & 31;
    int Mw = (warp >> 1) * 32, Nw = (warp & 1) * 32;
    int g = lane >> 2, t4 = lane & 3;

    float4 pa[2]; uint2 pbh, pbl;
    {
#pragma unroll
        for (int l = 0; l < 2; l++) {
            int f = tid + l * 256; int r = f >> 2, k4 = f & 3;
            int gr = rowBase + r; if (gr >= NNODES) gr = NNODES - 1;
            pa[l] = *(const float4*)&Z[gr * DDIM + k4 * 4];
        }
        int n = tid >> 2, kk2 = tid & 3;
        pbh = *(const uint2*)&g_UtH[n * (DDIM / 2) + kk2 * 2];
        pbl = *(const uint2*)&g_UtL[n * (DDIM / 2) + kk2 * 2];
    }
    float acc[8][4];
#pragma unroll
    for (int i = 0; i < 8; i++)
#pragma unroll
        for (int j = 0; j < 4; j++) acc[i][j] = 0.f;

    for (int kt = 0; kt < 16; kt++) {
#pragma unroll
        for (int l = 0; l < 2; l++) {
            int f = tid + l * 256; int r = f >> 2, k4 = f & 3;
            uint32_t h01, h23, l01, l23;
            split_pack4(pa[l], h01, h23, l01, l23);
            sm->sAh[r * 12 + k4 * 2] = h01; sm->sAh[r * 12 + k4 * 2 + 1] = h23;
            sm->sAl[r * 12 + k4 * 2] = l01; sm->sAl[r * 12 + k4 * 2 + 1] = l23;
        }
        {
            int n = tid >> 2, kk2 = tid & 3;
            *(uint2*)&sm->sBh[n * 12 + kk2 * 2] = pbh;
            *(uint2*)&sm->sBl[n * 12 + kk2 * 2] = pbl;
        }
        __syncthreads();
        if (kt < 15) {
            int k0 = (kt + 1) * 16;
#pragma unroll
            for (int l = 0; l < 2; l++) {
                int f = tid + l * 256; int r = f >> 2, k4 = f & 3;
                int gr = rowBase + r; if (gr >= NNODES) gr = NNODES - 1;
                pa[l] = *(const float4*)&Z[gr * DDIM + k0 + k4 * 4];
            }
            int n = tid >> 2, kk2 = tid & 3;
            pbh = *(const uint2*)&g_UtH[n * (DDIM / 2) + k0 / 2 + kk2 * 2];
            pbl = *(const uint2*)&g_UtL[n * (DDIM / 2) + k0 / 2 + kk2 * 2];
        }
        uint32_t Ah[2][4], Al[2][4], Bh[4][2], Bl[4][2];
#pragma unroll
        for (int mt = 0; mt < 2; mt++) {
            int r0 = Mw + mt * 16 + g;
            Ah[mt][0] = sm->sAh[r0 * 12 + t4];       Ah[mt][1] = sm->sAh[(r0 + 8) * 12 + t4];
            Ah[mt][2] = sm->sAh[r0 * 12 + 4 + t4];   Ah[mt][3] = sm->sAh[(r0 + 8) * 12 + 4 + t4];
            Al[mt][0] = sm->sAl[r0 * 12 + t4];       Al[mt][1] = sm->sAl[(r0 + 8) * 12 + t4];
            Al[mt][2] = sm->sAl[r0 * 12 + 4 + t4];   Al[mt][3] = sm->sAl[(r0 + 8) * 12 + 4 + t4];
        }
#pragma unroll
        for (int nt = 0; nt < 4; nt++) {
            int c0 = Nw + nt * 8 + g;
            Bh[nt][0] = sm->sBh[c0 * 12 + t4];  Bh[nt][1] = sm->sBh[c0 * 12 + 4 + t4];
            Bl[nt][0] = sm->sBl[c0 * 12 + t4];  Bl[nt][1] = sm->sBl[c0 * 12 + 4 + t4];
        }
#pragma unroll
        for (int mt = 0; mt < 2; mt++)
#pragma unroll
            for (int nt = 0; nt < 4; nt++) {
                float* d = acc[mt * 4 + nt];
                mma16(d, Ah[mt], Bh[nt]);
                mma16(d, Ah[mt], Bl[nt]);
                mma16(d, Al[mt], Bh[nt]);
            }
        __syncthreads();
    }
#pragma unroll
    for (int mt = 0; mt < 2; mt++)
#pragma unroll
        for (int nt = 0; nt < 4; nt++) {
            int gr0 = rowBase + Mw + mt * 16 + g;
            int c = Nw + nt * 8 + 2 * t4;
            float* d = acc[mt * 4 + nt];
            if (gr0 < NNODES)     *(float2*)&g_ZU[gr0 * CDIM + c]       = make_float2(d[0], d[1]);
            if (gr0 + 8 < NNODES) *(float2*)&g_ZU[(gr0 + 8) * CDIM + c] = make_float2(d[2], d[3]);
        }
}

// ================= merged kernels =================

// k0: zero counts ALONE (must fully precede hist — same-launch merge raced)
__global__ void k0() {
    int t = blockIdx.x * 256 + threadIdx.x;
    if (t < NNODES) g_cnt[t] = 0;
}

__global__ void k1(const float* __restrict__ U, const float* __restrict__ hw,
                   const int* __restrict__ ei, int E) {
    int b = blockIdx.x;
    if (b < 64)      d_prep(b, U, hw);
    else if (b < 96) d_prepT(b - 64, U);
    else             d_hist(b - 96, ei, E);
}

__global__ void k2(const float* __restrict__ Z, const float* __restrict__ A) {
    __shared__ SM_M smM;
    __shared__ int s_warp[8];
    __shared__ SM_ZU smZ;
    int b = blockIdx.x;
    if (b < 64)        d_m1(b, A, &smM);
    else if (b < 162)  d_scan1(b - 64, s_warp);
    else               d_zu(b - 162, Z, &smZ);
}

__global__ void k3(const float* __restrict__ A) {
    __shared__ SM_M smM;
    __shared__ int sw[4];
    int b = blockIdx.x;
    if (b < 64) d_m2(b, A, &smM);
    else        d_scan2(sw);
}

__global__ void k4(int E) {
    __shared__ SM_M smM;
    int b = blockIdx.x;
    if (b < 16) d_wm(b, &smM);
    else        d_scan3(b - 16, E);
}

__global__ void k5(const int* __restrict__ ei, int E) {
    int t = blockIdx.x * 256 + threadIdx.x;
    if (t < E) {
        int dst = ei[E + t];
        int pos = atomicAdd(&g_cursor[dst], 1);
        g_srcl[pos] = ei[t];
    }
}

// ---- agg: warp per node, 4-edge unroll ----
__global__ void k6() {
    int warp = (blockIdx.x * blockDim.x + threadIdx.x) >> 5;
    if (warp >= NNODES) return;
    int l = threadIdx.x & 31;
    float2 zd = *(const float2*)&g_ZU[warp * CDIM + l * 2];
    float ax = 0.f, ay = 0.f, ss = 0.f;
    int i = g_off[warp], end = g_off[warp + 1];
    for (; i + 3 < end; i += 4) {
        int s0 = g_srcl[i], s1 = g_srcl[i + 1], s2 = g_srcl[i + 2], s3 = g_srcl[i + 3];
        float2 a = *(const float2*)&g_ZU[s0 * CDIM + l * 2];
        float2 b = *(const float2*)&g_ZU[s1 * CDIM + l * 2];
        float2 c = *(const float2*)&g_ZU[s2 * CDIM + l * 2];
        float2 d = *(const float2*)&g_ZU[s3 * CDIM + l * 2];
        float p0 = a.x * zd.x + a.y * zd.y;
        float p1 = b.x * zd.x + b.y * zd.y;
        float p2 = c.x * zd.x + c.y * zd.y;
        float p3 = d.x * zd.x + d.y * zd.y;
        p0 += __shfl_xor_sync(0xffffffff, p0, 1);  p1 += __shfl_xor_sync(0xffffffff, p1, 1);
        p2 += __shfl_xor_sync(0xffffffff, p2, 1);  p3 += __shfl_xor_sync(0xffffffff, p3, 1);
        p0 += __shfl_xor_sync(0xffffffff, p0, 2);  p1 += __shfl_xor_sync(0xffffffff, p1, 2);
        p2 += __shfl_xor_sync(0xffffffff, p2, 2);  p3 += __shfl_xor_sync(0xffffffff, p3, 2);
        p0 += __shfl_xor_sync(0xffffffff, p0, 4);  p1 += __shfl_xor_sync(0xffffffff, p1, 4);
        p2 += __shfl_xor_sync(0xffffffff, p2, 4);  p3 += __shfl_xor_sync(0xffffffff, p3, 4);
        float e0 = __expf(p0 * 0.25f), e1 = __expf(p1 * 0.25f);
        float e2 = __expf(p2 * 0.25f), e3 = __expf(p3 * 0.25f);
        ss += (e0 + e1) + (e2 + e3);
        ax += e0 * a.x + e1 * b.x + e2 * c.x + e3 * d.x;
        ay += e0 * a.y + e1 * b.y + e2 * c.y + e3 * d.y;
    }
    for (; i < end; i++) {
        int s0 = g_srcl[i];
        float2 a = *(const float2*)&g_ZU[s0 * CDIM + l * 2];
        float p0 = a.x * zd.x + a.y * zd.y;
        p0 += __shfl_xor_sync(0xffffffff, p0, 1);
        p0 += __shfl_xor_sync(0xffffffff, p0, 2);
        p0 += __shfl_xor_sync(0xffffffff, p0, 4);
        float e0 = __expf(p0 * 0.25f);
        ss += e0; ax += e0 * a.x; ay += e0 * a.y;
    }
    float inv = 1.f / (ss + 1e-16f);
    *(float2*)&g_agg[warp * CDIM + l * 2] = make_float2(ax * inv, ay * inv);
}

// ======== final GEMM: out = relu([Z|Agg] @ G - 0.05) via bf16-split mma ========
__global__ __launch_bounds__(256, 1) void k_final(const float* __restrict__ Z, float* __restrict__ out) {
    __shared__ uint32_t sAh[128 * 12], sAl[128 * 12];
    __shared__ uint32_t sBh[128 * 12], sBl[128 * 12];
    int tid = threadIdx.x;
    int rowBase = blockIdx.x * 128;
    int colBase = blockIdx.y * 128;
    int warp = tid >> 5, lane = tid & 31;
    int Mw = (warp >> 2) * 64, Nw = (warp & 3) * 32;
    int g = lane >> 2, t4 = lane & 3;

    float4 pa[2]; uint2 pbh[2], pbl[2];
    {
#pragma unroll
        for (int l = 0; l < 2; l++) {
            int f = tid + l * 256; int r = f >> 2, k4 = f & 3;
            int gr = rowBase + r; if (gr >= NNODES) gr = NNODES - 1;
            pa[l] = *(const float4*)&Z[gr * DDIM + k4 * 4];
        }
#pragma unroll
        for (int l = 0; l < 2; l++) {
            int f = tid + l * 256; int n = f >> 2, kk2 = f & 3;
            pbh[l] = *(const uint2*)&g_GtH[(colBase + n) * (XDIM / 2) + kk2 * 2];
            pbl[l] = *(const uint2*)&g_GtL[(colBase + n) * (XDIM / 2) + kk2 * 2];
        }
    }
    float acc[16][4];
#pragma unroll
    for (int i = 0; i < 16; i++)
#pragma unroll
        for (int j = 0; j < 4; j++) acc[i][j] = 0.f;

    for (int kt = 0; kt < 20; kt++) {
#pragma unroll
        for (int l = 0; l < 2; l++) {
            int f = tid + l * 256; int r = f >> 2, k4 = f & 3;
            uint32_t h01, h23, l01, l23;
            split_pack4(pa[l], h01, h23, l01, l23);
            sAh[r * 12 + k4 * 2] = h01; sAh[r * 12 + k4 * 2 + 1] = h23;
            sAl[r * 12 + k4 * 2] = l01; sAl[r * 12 + k4 * 2 + 1] = l23;
        }
#pragma unroll
        for (int l = 0; l < 2; l++) {
            int f = tid + l * 256; int n = f >> 2, kk2 = f & 3;
            *(uint2*)&sBh[n * 12 + kk2 * 2] = pbh[l];
            *(uint2*)&sBl[n * 12 + kk2 * 2] = pbl[l];
        }
        __syncthreads();
        if (kt < 19) {
            int kn = kt + 1;
            const float* Aptr; int ld, koff;
            if (kn < 16) { Aptr = Z;     ld = DDIM; koff = kn * 16; }
            else         { Aptr = g_agg; ld = CDIM; koff = kn * 16 - DDIM; }
#pragma unroll
            for (int l = 0; l < 2; l++) {
                int f = tid + l * 256; int r = f >> 2, k4 = f & 3;
                int gr = rowBase + r; if (gr >= NNODES) gr = NNODES - 1;
                pa[l] = *(const float4*)&Aptr[gr * ld + koff + k4 * 4];
            }
#pragma unroll
            for (int l = 0; l < 2; l++) {
                int f = tid + l * 256; int n = f >> 2, kk2 = f & 3;
                pbh[l] = *(const uint2*)&g_GtH[(colBase + n) * (XDIM / 2) + kn * 8 + kk2 * 2];
                pbl[l] = *(const uint2*)&g_GtL[(colBase + n) * (XDIM / 2) + kn * 8 + kk2 * 2];
            }
        }
        uint32_t Ah[4][4], Al[4][4], Bh[4][2], Bl[4][2];
#pragma unroll
        for (int mt = 0; mt < 4; mt++) {
            int r0 = Mw + mt * 16 + g;
            Ah[mt][0] = sAh[r0 * 12 + t4];       Ah[mt][1] = sAh[(r0 + 8) * 12 + t4];
            Ah[mt][2] = sAh[r0 * 12 + 4 + t4];   Ah[mt][3] = sAh[(r0 + 8) * 12 + 4 + t4];
            Al[mt][0] = sAl[r0 * 12 + t4];       Al[mt][1] = sAl[(r0 + 8) * 12 + t4];
            Al[mt][2] = sAl[r0 * 12 + 4 + t4];   Al[mt][3] = sAl[(r0 + 8) * 12 + 4 + t4];
        }
#pragma unroll
        for (int nt = 0; nt < 4; nt++) {
            int c0 = Nw + nt * 8 + g;
            Bh[nt][0] = sBh[c0 * 12 + t4];  Bh[nt][1] = sBh[c0 * 12 + 4 + t4];
            Bl[nt][0] = sBl[c0 * 12 + t4];  Bl[nt][1] = sBl[c0 * 12 + 4 + t4];
        }
#pragma unroll
        for (int mt = 0; mt < 4; mt++)
#pragma unroll
            for (int nt = 0; nt < 4; nt++) {
                float* d = acc[mt * 4 + nt];
                mma16(d, Ah[mt], Bh[nt]);
                mma16(d, Ah[mt], Bl[nt]);
                mma16(d, Al[mt], Bh[nt]);
            }
        __syncthreads();
    }
#pragma unroll
    for (int mt = 0; mt < 4; mt++)
#pragma unroll
        for (int nt = 0; nt < 4; nt++) {
            int gr0 = rowBase + Mw + mt * 16 + g;
            int c = colBase + Nw + nt * 8 + 2 * t4;
            float* d = acc[mt * 4 + nt];
            if (gr0 < NNODES)
                *(float2*)&out[gr0 * DDIM + c] =
                    make_float2(fmaxf(d[0] - 0.05f, 0.f), fmaxf(d[1] - 0.05f, 0.f));
            if (gr0 + 8 < NNODES)
                *(float2*)&out[(gr0 + 8) * DDIM + c] =
                    make_float2(fmaxf(d[2] - 0.05f, 0.f), fmaxf(d[3] - 0.05f, 0.f));
        }
}

extern "C" void kernel_launch(void* const* d_in, const int* in_sizes, int n_in,
                              void* d_out, int out_size) {
    const float* Z    = (const float*)d_in[0];
    const float* U    = (const float*)d_in[1];
    const float* Dmat = (const float*)d_in[2];
    const float* hw   = (const float*)d_in[3];
    const int*   ei   = (const int*)d_in[4];
    int E = in_sizes[4] / 2;
    float* out = (float*)d_out;

    int histBlocks = (E + 255) / 256;
    k0<<<(NNODES + 255) / 256, 256>>>();                    // zero counts (must precede hist)
    k1<<<96 + histBlocks, 256>>>(U, hw, ei, E);             // prep | prepT | hist
    k2<<<162 + (NNODES + 127) / 128, 256>>>(Z, Dmat);       // m1 | scan1 | zu
    k3<<<65, 256>>>(Dmat);                                  // m2 | scan2
    k4<<<16 + (NNODES + 255) / 256, 256>>>(E);              // wm | scan3
    k5<<<histBlocks, 256>>>(ei, E);                         // scatter
    k6<<<(NNODES * 32 + 255) / 256, 256>>>();               // agg
    k_final<<<dim3((NNODES + 127) / 128, DDIM / 128), 256>>>(Z, out);
}